// round 11
// baseline (speedup 1.0000x reference)
#include <cuda_runtime.h>
#include <cuda_bf16.h>
#include <cuda_fp16.h>
#include <mma.h>
#include <cmath>
#include <cstdint>

using namespace nvcuda;
typedef __nv_bfloat16 bf16;

// ---------------- problem constants ----------------
#define NWIN   8192
#define TTOK   401408
#define HWI    224
#define HWSQ   50176
#define DIMC   192

// scratch (allocation-free static device arrays)
__device__ __half g_qkvh [(size_t)TTOK * 576];   // QKV (scaled/biased, fp16)
__device__ __half g_attnh[(size_t)TTOK * DIMC];  // attention out (fp16)
__device__ float  g_h1  [(size_t)TTOK * DIMC];   // x + attn branch (fp32)
__device__ bf16   g_h1n [(size_t)TTOK * DIMC];   // LN2(h1) bf16
__device__ __half g_qkvw_h[192 * 576];
__device__ __half g_projw_h[192 * 192];
__device__ bf16   g_fc1w_b [192 * 768];
__device__ bf16   g_fc2w_b [768 * 192];
__device__ float  g_bias   [6 * 49 * 49];

// fp16 fragments (attention path)
typedef wmma::fragment<wmma::matrix_a,16,16,16,__half,wmma::row_major> FragAh;
typedef wmma::fragment<wmma::matrix_b,16,16,16,__half,wmma::row_major> FragBh;
typedef wmma::fragment<wmma::matrix_b,16,16,16,__half,wmma::col_major> FragBTh;
typedef wmma::fragment<wmma::accumulator,16,16,16,float> FragCf;
// bf16 fragments (MLP path)
typedef wmma::fragment<wmma::matrix_a,16,16,16,bf16,wmma::row_major> FragAb;
typedef wmma::fragment<wmma::matrix_b,16,16,16,bf16,wmma::row_major> FragBb;

// ---------------- prelude ----------------
#define W_QKV 110592
#define W_PRJ  36864
#define W_FC1 147456
#define W_FC2 147456
#define N_BIAS 14406
#define PRE_TOT (W_QKV + W_PRJ + W_FC1 + W_FC2 + N_BIAS)

__global__ void prelude(const float* __restrict__ qkvw, const float* __restrict__ projw,
                        const float* __restrict__ fc1w, const float* __restrict__ fc2w,
                        const float* __restrict__ rpb,  const int* __restrict__ relidx)
{
    int i = blockIdx.x * blockDim.x + threadIdx.x;
    if (i < W_QKV) { g_qkvw_h[i] = __float2half_rn(qkvw[i]); return; }
    i -= W_QKV;
    if (i < W_PRJ) { g_projw_h[i] = __float2half_rn(projw[i]); return; }
    i -= W_PRJ;
    if (i < W_FC1) { g_fc1w_b[i] = __float2bfloat16(fc1w[i]); return; }
    i -= W_FC1;
    if (i < W_FC2) { g_fc2w_b[i] = __float2bfloat16(fc2w[i]); return; }
    i -= W_FC2;
    if (i < N_BIAS) {
        int h = i / 2401, rj = i - h * 2401;
        g_bias[i] = rpb[relidx[rj] * 6 + h];
    }
}

// ============================================================================
// Kernel A: batched QKV GEMM, fp16, 64-token tiles (6272 CTAs, 256 thr,
// 2 CTAs/SM). smem: xnf f32[64][196]@0 (50176, st f32[64][100] overlays);
// xh half[64][200]@50176 (25600). total 75776
// ============================================================================
#define XN_LD 196
#define XH_LD 200
#define ST_LD 100
#define QKV_SMEM 75776

__global__ void __launch_bounds__(256, 2)
qkv_gemm(const float* __restrict__ x,
         const float* __restrict__ ln1w, const float* __restrict__ ln1b,
         const float* __restrict__ qkvb)
{
    extern __shared__ char smc[];
    float*  xnf = (float*)smc;
    float*  st  = (float*)smc;                 // overlay (used after LN1)
    __half* xh  = (__half*)(smc + 50176);

    const int tid  = threadIdx.x;
    const int wid  = tid >> 5;
    const int lane = tid & 31;
    const int t0   = blockIdx.x * 64;

    // gather x (fp32): thread owns row r=tid&63, strides c by 4
    {
        const int r = tid & 63;
        const int t = t0 + r;
        const int win = t / 49, pos = t - win * 49;
        const int b = win >> 10, wh = (win >> 5) & 31, ww = win & 31;
        const int pi = pos / 7;
        const float* src = x + (size_t)b * DIMC * HWSQ + (wh * 7 + pi) * HWI + (ww * 7 + pos - pi * 7);
        for (int c = tid >> 6; c < DIMC; c += 4)
            xnf[r * XN_LD + c] = src[(size_t)c * HWSQ];
    }
    __syncthreads();

    // LN1 (fp32 stats) -> fp16 A operand
    for (int r = wid; r < 64; r += 8) {
        float v[6]; float s = 0.f;
#pragma unroll
        for (int q = 0; q < 6; q++) { v[q] = xnf[r * XN_LD + lane + q * 32]; s += v[q]; }
#pragma unroll
        for (int o = 16; o; o >>= 1) s += __shfl_xor_sync(~0u, s, o);
        float mu = s * (1.f / 192.f);
        float vs = 0.f;
#pragma unroll
        for (int q = 0; q < 6; q++) { float d = v[q] - mu; vs += d * d; }
#pragma unroll
        for (int o = 16; o; o >>= 1) vs += __shfl_xor_sync(~0u, vs, o);
        float rs = rsqrtf(vs * (1.f / 192.f) + 1e-5f);
#pragma unroll
        for (int q = 0; q < 6; q++) {
            int c = lane + q * 32;
            xh[r * XH_LD + c] = __float2half_rn((v[q] - mu) * rs * ln1w[c] + ln1b[c]);
        }
    }
    __syncthreads();

    const int rtg = wid & 3;     // row tile (16 rows)
    const int ctg = wid >> 2;    // 0/1
    const float scale = 0.17677669529663687f;

    for (int chunk = 0; chunk < 6; chunk++) {
        FragCf acc[3];
#pragma unroll
        for (int j = 0; j < 3; j++) wmma::fill_fragment(acc[j], 0.f);

        for (int k = 0; k < 12; k++) {
            FragAh af;
            wmma::load_matrix_sync(af, xh + rtg * 16 * XH_LD + k * 16, XH_LD);
#pragma unroll
            for (int j = 0; j < 3; j++) {
                FragBh bf;
                wmma::load_matrix_sync(bf, g_qkvw_h + (size_t)k * 16 * 576 + chunk * 96 + (ctg * 3 + j) * 16, 576);
                wmma::mma_sync(acc[j], af, bf, acc[j]);
            }
        }
#pragma unroll
        for (int j = 0; j < 3; j++)
            wmma::store_matrix_sync(st + rtg * 16 * ST_LD + (ctg * 3 + j) * 16,
                                    acc[j], ST_LD, wmma::mem_row_major);
        __syncthreads();

        // epilogue: bias, q-scale, fp16 round -> g_qkvh
        for (int idx = tid; idx < 64 * 96; idx += 256) {
            int r = idx / 96, cl = idx - r * 96;
            int gc = chunk * 96 + cl;
            float v = st[r * ST_LD + cl] + qkvb[gc];
            if (gc < 192) v *= scale;
            g_qkvh[(size_t)(t0 + r) * 576 + gc] = __float2half_rn(v);
        }
        __syncthreads();
    }
}

// ============================================================================
// Kernel B: per window-head attention, fp16 (grid (NWIN,6), 128 thr, 42KB,
// 5 CTAs/SM) — unchanged from round 10.
// ============================================================================
#define H_LDH 40
#define PB_LD 72
#define SC_LD 68
#define AH_SMEM 41984

__global__ void __launch_bounds__(128, 5)
attn_heads()
{
    extern __shared__ char smc[];
    __half* qs = (__half*)smc;
    __half* ks = (__half*)(smc + 5120);
    __half* vs = (__half*)(smc + 10240);
    __half* pb = (__half*)(smc + 15360);
    float*  sc = (float*)(smc + 24576);

    const int tid  = threadIdx.x;
    const int wid  = tid >> 5;
    const int lane = tid & 31;
    const int win  = blockIdx.x;
    const int h    = blockIdx.y;

    {
        const __half* base = g_qkvh + (size_t)win * 49 * 576 + h * 32;
        for (int idx = tid; idx < 3 * 49 * 4; idx += 128) {
            int m = idx / 196, rem = idx - m * 196;
            int r = rem >> 2, c8 = rem & 3;
            float4 v = *(const float4*)(base + (size_t)r * 576 + m * 192 + c8 * 8);
            __half* dst = (m == 0 ? qs : (m == 1 ? ks : vs));
            *(float4*)(dst + r * H_LDH + c8 * 8) = v;
        }
        float4 z = make_float4(0.f, 0.f, 0.f, 0.f);
        for (int idx = tid; idx < 3 * 15 * 4; idx += 128) {
            int m = idx / 60, rem = idx - m * 60;
            int r = 49 + (rem >> 2), c8 = rem & 3;
            __half* dst = (m == 0 ? qs : (m == 1 ? ks : vs));
            *(float4*)(dst + r * H_LDH + c8 * 8) = z;
        }
        for (int idx = tid; idx < 576; idx += 128)
            *(float4*)(pb + idx * 8) = z;
    }
    __syncthreads();

    {
        FragAh af[2];
#pragma unroll
        for (int k = 0; k < 2; k++)
            wmma::load_matrix_sync(af[k], qs + wid * 16 * H_LDH + k * 16, H_LDH);
#pragma unroll
        for (int ct = 0; ct < 4; ct++) {
            FragCf acc; wmma::fill_fragment(acc, 0.f);
#pragma unroll
            for (int k = 0; k < 2; k++) {
                FragBTh bf; wmma::load_matrix_sync(bf, ks + ct * 16 * H_LDH + k * 16, H_LDH);
                wmma::mma_sync(acc, af[k], bf, acc);
            }
            wmma::store_matrix_sync(sc + wid * 16 * SC_LD + ct * 16, acc, SC_LD, wmma::mem_row_major);
        }
    }
    __syncthreads();

    {
        const float* bh = g_bias + h * 2401;
        for (int r = wid; r < 49; r += 4) {
            float* srow = sc + r * SC_LD;
            int j0 = lane, j1 = lane + 32;
            float v0 = srow[j0] + bh[r * 49 + j0];
            float v1 = (j1 < 49) ? srow[j1] + bh[r * 49 + j1] : -1e30f;
            float m = fmaxf(v0, v1);
#pragma unroll
            for (int o = 16; o; o >>= 1) m = fmaxf(m, __shfl_xor_sync(~0u, m, o));
            float e0 = expf(v0 - m);
            float e1 = (j1 < 49) ? expf(v1 - m) : 0.f;
            float s = e0 + e1;
#pragma unroll
            for (int o = 16; o; o >>= 1) s += __shfl_xor_sync(~0u, s, o);
            float inv = 1.f / s;
            __half* prow = pb + r * PB_LD;
            prow[j0] = __float2half_rn(e0 * inv);
            if (j1 < 49) prow[j1] = __float2half_rn(e1 * inv);
        }
    }
    __syncthreads();

    {
        FragAh pf[4];
#pragma unroll
        for (int k = 0; k < 4; k++)
            wmma::load_matrix_sync(pf[k], pb + wid * 16 * PB_LD + k * 16, PB_LD);
#pragma unroll
        for (int ct = 0; ct < 2; ct++) {
            FragCf acc; wmma::fill_fragment(acc, 0.f);
#pragma unroll
            for (int k = 0; k < 4; k++) {
                FragBh bf; wmma::load_matrix_sync(bf, vs + k * 16 * H_LDH + ct * 16, H_LDH);
                wmma::mma_sync(acc, pf[k], bf, acc);
            }
            wmma::store_matrix_sync(sc + wid * 16 * SC_LD + ct * 16, acc, SC_LD, wmma::mem_row_major);
        }
    }
    __syncthreads();

    {
        __half* base = g_attnh + (size_t)win * 49 * DIMC + h * 32;
        for (int idx = tid; idx < 49 * 16; idx += 128) {
            int r = idx >> 4, c2 = idx & 15;
            __half2 h2 = __floats2half2_rn(sc[r * SC_LD + c2 * 2], sc[r * SC_LD + c2 * 2 + 1]);
            *(__half2*)(base + (size_t)r * DIMC + c2 * 2) = h2;
        }
    }
}

// ============================================================================
// Kernel C: proj (fp16) + residual + LN2, 64-token tiles (6272 CTAs, 256 thr,
// 2 CTAs/SM). smem: xh half[64][200]@0 (25600); st f32[64][196]@25600 (50176).
// total 75776
// ============================================================================
#define PJ_LD 196
#define PROJ_SMEM 75776

__global__ void __launch_bounds__(256, 2)
proj_ln2(const float* __restrict__ x,
         const float* __restrict__ projb,
         const float* __restrict__ ln2w, const float* __restrict__ ln2b)
{
    extern __shared__ char smc[];
    __half* xh = (__half*)smc;
    float*  st = (float*)(smc + 25600);

    const int tid  = threadIdx.x;
    const int wid  = tid >> 5;
    const int lane = tid & 31;
    const int t0   = blockIdx.x * 64;

    // load attn-out (fp16, coalesced)
    {
        const float4* src = (const float4*)(g_attnh + (size_t)t0 * DIMC);
        for (int idx = tid; idx < 64 * 24; idx += 256) {
            int r = idx / 24, c8 = idx - r * 24;
            *(float4*)(xh + r * XH_LD + c8 * 8) = src[idx];
        }
    }
    __syncthreads();

    // proj GEMM fp16: warps rtg(4) x ctg(2), each warp 6 ct accumulators
    const int rtg = wid & 3;
    const int ctg = wid >> 2;
    {
        FragCf acc[6];
#pragma unroll
        for (int j = 0; j < 6; j++) wmma::fill_fragment(acc[j], 0.f);

        for (int k = 0; k < 12; k++) {
            FragAh af;
            wmma::load_matrix_sync(af, xh + rtg * 16 * XH_LD + k * 16, XH_LD);
#pragma unroll
            for (int j = 0; j < 6; j++) {
                FragBh bf;
                wmma::load_matrix_sync(bf, g_projw_h + (size_t)k * 16 * 192 + (ctg + 2 * j) * 16, 192);
                wmma::mma_sync(acc[j], af, bf, acc[j]);
            }
        }
#pragma unroll
        for (int j = 0; j < 6; j++)
            wmma::store_matrix_sync(st + rtg * 16 * PJ_LD + (ctg + 2 * j) * 16,
                                    acc[j], PJ_LD, wmma::mem_row_major);
    }
    __syncthreads();

    // residual: st += x + projb
    {
        const int r = tid & 63;
        const int t = t0 + r;
        const int win = t / 49, pos = t - win * 49;
        const int b = win >> 10, wh = (win >> 5) & 31, ww = win & 31;
        const int pi = pos / 7;
        const float* src = x + (size_t)b * DIMC * HWSQ + (wh * 7 + pi) * HWI + (ww * 7 + pos - pi * 7);
        for (int c = tid >> 6; c < DIMC; c += 4)
            st[r * PJ_LD + c] += src[(size_t)c * HWSQ] + projb[c];
    }
    __syncthreads();

    // LN2 + write h1 (fp32) / h1n (bf16)
    for (int r = wid; r < 64; r += 8) {
        float v[6]; float s = 0.f;
#pragma unroll
        for (int q = 0; q < 6; q++) { v[q] = st[r * PJ_LD + lane + q * 32]; s += v[q]; }
#pragma unroll
        for (int o = 16; o; o >>= 1) s += __shfl_xor_sync(~0u, s, o);
        float mu = s * (1.f / 192.f);
        float vs = 0.f;
#pragma unroll
        for (int q = 0; q < 6; q++) { float d = v[q] - mu; vs += d * d; }
#pragma unroll
        for (int o = 16; o; o >>= 1) vs += __shfl_xor_sync(~0u, vs, o);
        float rs = rsqrtf(vs * (1.f / 192.f) + 1e-5f);
        size_t base = (size_t)(t0 + r) * DIMC;
#pragma unroll
        for (int q = 0; q < 6; q++) {
            int c = lane + q * 32;
            g_h1 [base + c] = v[q];
            g_h1n[base + c] = __float2bfloat16((v[q] - mu) * rs * ln2w[c] + ln2b[c]);
        }
    }
}

// ============================================================================
// Kernel D: round-4 MLP (256 threads, 2 CTAs/SM, bf16) — unchanged.
// ============================================================================
#define AS_LD 200
#define MD_LD 196
#define MLP_SMEM 101376

__global__ void __launch_bounds__(256, 2)
mlp_kernel(const float* __restrict__ fc1b, const float* __restrict__ fc2b,
           float* __restrict__ out)
{
    extern __shared__ char smc[];
    bf16*  as   = (bf16*)smc;
    float* mid  = (float*)(smc + 25600);
    bf16*  midb = (bf16*)(smc + 75776);

    const int tid = threadIdx.x;
    const int wid = tid >> 5;
    const int t0  = blockIdx.x * 64;
    const int rt  = wid & 3;
    const int ctb = wid >> 2;

    {
        const uint4* src = (const uint4*)g_h1n;
        uint4* dst = (uint4*)as;
        for (int idx = tid; idx < 64 * 24; idx += 256) {
            int r = idx / 24, c = idx - r * 24;
            dst[r * 25 + c] = src[(size_t)(t0 + r) * 24 + c];
        }
    }
    __syncthreads();

    wmma::fragment<wmma::accumulator,16,16,16,float> acc2[6];
#pragma unroll
    for (int j = 0; j < 6; j++) wmma::fill_fragment(acc2[j], 0.f);

    for (int chunk = 0; chunk < 4; chunk++) {
#pragma unroll
        for (int g = 0; g < 2; g++) {
            wmma::fragment<wmma::accumulator,16,16,16,float> acc[3];
#pragma unroll
            for (int j = 0; j < 3; j++) wmma::fill_fragment(acc[j], 0.f);
            for (int k = 0; k < 12; k++) {
                FragAb af; wmma::load_matrix_sync(af, as + rt * 16 * AS_LD + k * 16, AS_LD);
#pragma unroll
                for (int j = 0; j < 3; j++) {
                    int ct = ctb + 2 * (3 * g + j);
                    FragBb bf;
                    wmma::load_matrix_sync(bf, g_fc1w_b + (size_t)k * 16 * 768 + chunk * 192 + ct * 16, 768);
                    wmma::mma_sync(acc[j], af, bf, acc[j]);
                }
            }
#pragma unroll
            for (int j = 0; j < 3; j++) {
                int ct = ctb + 2 * (3 * g + j);
                wmma::store_matrix_sync(mid + rt * 16 * MD_LD + ct * 16, acc[j], MD_LD, wmma::mem_row_major);
            }
        }
        __syncthreads();

        for (int idx = tid; idx < 64 * 192; idx += 256) {
            int r = idx / 192, c = idx - r * 192;
            float v = mid[r * MD_LD + c] + fc1b[chunk * 192 + c];
            midb[r * AS_LD + c] = __float2bfloat16(0.5f * v * (1.f + erff(v * 0.70710678118654752f)));
        }
        __syncthreads();

        for (int kk = 0; kk < 12; kk++) {
            FragAb af; wmma::load_matrix_sync(af, midb + rt * 16 * AS_LD + kk * 16, AS_LD);
#pragma unroll
            for (int j = 0; j < 6; j++) {
                int ct = ctb + 2 * j;
                FragBb bf;
                wmma::load_matrix_sync(bf, g_fc2w_b + (size_t)(chunk * 192 + kk * 16) * 192 + ct * 16, 192);
                wmma::mma_sync(acc2[j], af, bf, acc2[j]);
            }
        }
        __syncthreads();
    }

#pragma unroll
    for (int j = 0; j < 6; j++) {
        int ct = ctb + 2 * j;
        wmma::store_matrix_sync(mid + rt * 16 * MD_LD + ct * 16, acc2[j], MD_LD, wmma::mem_row_major);
    }
    __syncthreads();

    for (int idx = tid; idx < 64 * 192; idx += 256) {
        int r = idx & 63;
        int c = idx >> 6;
        int t = t0 + r;
        int win = t / 49; int pos = t - win * 49;
        int b  = win >> 10;
        int wh = (win >> 5) & 31;
        int ww = win & 31;
        int pi = pos / 7;
        int hh = wh * 7 + pi;
        int wx = ww * 7 + (pos - pi * 7);
        out[((size_t)(b * DIMC + c)) * HWSQ + hh * HWI + wx] =
            mid[r * MD_LD + c] + g_h1[(size_t)t * 192 + c] + fc2b[c];
    }
}

// ============================================================================
extern "C" void kernel_launch(void* const* d_in, const int* in_sizes, int n_in,
                              void* d_out, int out_size)
{
    (void)in_sizes; (void)n_in; (void)out_size;
    const float* x     = (const float*)d_in[0];
    const float* ln1w  = (const float*)d_in[1];
    const float* ln1b  = (const float*)d_in[2];
    const float* qkvw  = (const float*)d_in[3];
    const float* qkvb  = (const float*)d_in[4];
    const float* projw = (const float*)d_in[5];
    const float* projb = (const float*)d_in[6];
    const float* rpb   = (const float*)d_in[7];
    const float* ln2w  = (const float*)d_in[8];
    const float* ln2b  = (const float*)d_in[9];
    const float* fc1w  = (const float*)d_in[10];
    const float* fc1b  = (const float*)d_in[11];
    const float* fc2w  = (const float*)d_in[12];
    const float* fc2b  = (const float*)d_in[13];
    const int*   ridx  = (const int*)  d_in[14];
    float* out = (float*)d_out;

    cudaFuncSetAttribute(qkv_gemm,   cudaFuncAttributeMaxDynamicSharedMemorySize, QKV_SMEM);
    cudaFuncSetAttribute(attn_heads, cudaFuncAttributeMaxDynamicSharedMemorySize, AH_SMEM);
    cudaFuncSetAttribute(proj_ln2,   cudaFuncAttributeMaxDynamicSharedMemorySize, PROJ_SMEM);
    cudaFuncSetAttribute(mlp_kernel, cudaFuncAttributeMaxDynamicSharedMemorySize, MLP_SMEM);

    prelude<<<(PRE_TOT + 511) / 512, 512>>>(qkvw, projw, fc1w, fc2w, rpb, ridx);

    qkv_gemm<<<TTOK / 64, 256, QKV_SMEM>>>(x, ln1w, ln1b, qkvb);

    dim3 ag(NWIN, 6);
    attn_heads<<<ag, 128, AH_SMEM>>>();

    proj_ln2<<<TTOK / 64, 256, PROJ_SMEM>>>(x, projb, ln2w, ln2b);

    mlp_kernel<<<TTOK / 64, 256, MLP_SMEM>>>(fc1b, fc2b, out);
}

// round 12
// speedup vs baseline: 1.4734x; 1.4734x over previous
#include <cuda_runtime.h>
#include <cuda_bf16.h>
#include <cuda_fp16.h>
#include <mma.h>
#include <cmath>
#include <cstdint>

using namespace nvcuda;
typedef __nv_bfloat16 bf16;

// ---------------- problem constants ----------------
#define NWIN   8192
#define TTOK   401408
#define HWI    224
#define HWSQ   50176
#define DIMC   192

// scratch (allocation-free static device arrays)
__device__ __half g_qkvh [(size_t)TTOK * 576];   // QKV (scaled/biased, fp16)
__device__ __half g_attnh[(size_t)TTOK * DIMC];  // attention out (fp16)
__device__ float  g_h1  [(size_t)TTOK * DIMC];   // x + attn branch (fp32)
__device__ bf16   g_h1n [(size_t)TTOK * DIMC];   // LN2(h1) bf16
__device__ __half g_qkvw_h[192 * 576];
__device__ __half g_projw_h[192 * 192];
__device__ bf16   g_fc1w_b [192 * 768];
__device__ bf16   g_fc2w_b [768 * 192];
__device__ float  g_bias   [6 * 49 * 49];

// fp16 fragments (attention path)
typedef wmma::fragment<wmma::matrix_a,16,16,16,__half,wmma::row_major> FragAh;
typedef wmma::fragment<wmma::matrix_b,16,16,16,__half,wmma::row_major> FragBh;
typedef wmma::fragment<wmma::matrix_b,16,16,16,__half,wmma::col_major> FragBTh;
typedef wmma::fragment<wmma::accumulator,16,16,16,float> FragCf;
// bf16 fragments (MLP path)
typedef wmma::fragment<wmma::matrix_a,16,16,16,bf16,wmma::row_major> FragAb;
typedef wmma::fragment<wmma::matrix_b,16,16,16,bf16,wmma::row_major> FragBb;

// ---------------- prelude ----------------
#define W_QKV 110592
#define W_PRJ  36864
#define W_FC1 147456
#define W_FC2 147456
#define N_BIAS 14406
#define PRE_TOT (W_QKV + W_PRJ + W_FC1 + W_FC2 + N_BIAS)

__global__ void prelude(const float* __restrict__ qkvw, const float* __restrict__ projw,
                        const float* __restrict__ fc1w, const float* __restrict__ fc2w,
                        const float* __restrict__ rpb,  const int* __restrict__ relidx)
{
    int i = blockIdx.x * blockDim.x + threadIdx.x;
    if (i < W_QKV) { g_qkvw_h[i] = __float2half_rn(qkvw[i]); return; }
    i -= W_QKV;
    if (i < W_PRJ) { g_projw_h[i] = __float2half_rn(projw[i]); return; }
    i -= W_PRJ;
    if (i < W_FC1) { g_fc1w_b[i] = __float2bfloat16(fc1w[i]); return; }
    i -= W_FC1;
    if (i < W_FC2) { g_fc2w_b[i] = __float2bfloat16(fc2w[i]); return; }
    i -= W_FC2;
    if (i < N_BIAS) {
        int h = i / 2401, rj = i - h * 2401;
        g_bias[i] = rpb[relidx[rj] * 6 + h];
    }
}

// ============================================================================
// Kernel A: batched QKV GEMM, fp16, 64-token tiles (6272 CTAs, 256 thr,
// 2 CTAs/SM), warp tile 2rt x 3ct (0.83 loads/mma), 3 chunks of 192 cols.
// smem: xnf f32[64][196]@0 (50176, st f32[64][196] overlays);
// xh half[64][200]@50176 (25600). total 75776
// ============================================================================
#define XN_LD 196
#define XH_LD 200
#define ST_LD 196
#define QKV_SMEM 75776

__global__ void __launch_bounds__(256, 2)
qkv_gemm(const float* __restrict__ x,
         const float* __restrict__ ln1w, const float* __restrict__ ln1b,
         const float* __restrict__ qkvb)
{
    extern __shared__ char smc[];
    float*  xnf = (float*)smc;
    float*  st  = (float*)smc;                 // overlay (used after LN1)
    __half* xh  = (__half*)(smc + 50176);

    const int tid  = threadIdx.x;
    const int wid  = tid >> 5;
    const int lane = tid & 31;
    const int t0   = blockIdx.x * 64;

    // gather x (fp32): thread owns row r=tid&63, strides c by 4
    {
        const int r = tid & 63;
        const int t = t0 + r;
        const int win = t / 49, pos = t - win * 49;
        const int b = win >> 10, wh = (win >> 5) & 31, ww = win & 31;
        const int pi = pos / 7;
        const float* src = x + (size_t)b * DIMC * HWSQ + (wh * 7 + pi) * HWI + (ww * 7 + pos - pi * 7);
        for (int c = tid >> 6; c < DIMC; c += 4)
            xnf[r * XN_LD + c] = src[(size_t)c * HWSQ];
    }
    __syncthreads();

    // LN1 (fp32 stats) -> fp16 A operand
    for (int r = wid; r < 64; r += 8) {
        float v[6]; float s = 0.f;
#pragma unroll
        for (int q = 0; q < 6; q++) { v[q] = xnf[r * XN_LD + lane + q * 32]; s += v[q]; }
#pragma unroll
        for (int o = 16; o; o >>= 1) s += __shfl_xor_sync(~0u, s, o);
        float mu = s * (1.f / 192.f);
        float vs = 0.f;
#pragma unroll
        for (int q = 0; q < 6; q++) { float d = v[q] - mu; vs += d * d; }
#pragma unroll
        for (int o = 16; o; o >>= 1) vs += __shfl_xor_sync(~0u, vs, o);
        float rs = rsqrtf(vs * (1.f / 192.f) + 1e-5f);
#pragma unroll
        for (int q = 0; q < 6; q++) {
            int c = lane + q * 32;
            xh[r * XH_LD + c] = __float2half_rn((v[q] - mu) * rs * ln1w[c] + ln1b[c]);
        }
    }
    __syncthreads();

    const int rtg = wid & 1;     // rows rtg*32 .. +31 (2 rt tiles)
    const int ctg = wid >> 1;    // 0..3, ct tiles ctg*3 .. +2 within chunk
    const float scale = 0.17677669529663687f;

    for (int chunk = 0; chunk < 3; chunk++) {
        FragCf acc[2][3];
#pragma unroll
        for (int i = 0; i < 2; i++)
#pragma unroll
            for (int j = 0; j < 3; j++) wmma::fill_fragment(acc[i][j], 0.f);

        for (int k = 0; k < 12; k++) {
            FragAh af[2];
#pragma unroll
            for (int i = 0; i < 2; i++)
                wmma::load_matrix_sync(af[i], xh + (rtg * 32 + i * 16) * XH_LD + k * 16, XH_LD);
#pragma unroll
            for (int j = 0; j < 3; j++) {
                FragBh bf;
                wmma::load_matrix_sync(bf, g_qkvw_h + (size_t)k * 16 * 576 + chunk * 192 + (ctg * 3 + j) * 16, 576);
#pragma unroll
                for (int i = 0; i < 2; i++)
                    wmma::mma_sync(acc[i][j], af[i], bf, acc[i][j]);
            }
        }
#pragma unroll
        for (int i = 0; i < 2; i++)
#pragma unroll
            for (int j = 0; j < 3; j++)
                wmma::store_matrix_sync(st + (rtg * 32 + i * 16) * ST_LD + (ctg * 3 + j) * 16,
                                        acc[i][j], ST_LD, wmma::mem_row_major);
        __syncthreads();

        // epilogue: bias, q-scale, fp16 round -> g_qkvh
        for (int idx = tid; idx < 64 * 192; idx += 256) {
            int r = idx / 192, cl = idx - r * 192;
            int gc = chunk * 192 + cl;
            float v = st[r * ST_LD + cl] + qkvb[gc];
            if (gc < 192) v *= scale;
            g_qkvh[(size_t)(t0 + r) * 576 + gc] = __float2half_rn(v);
        }
        __syncthreads();
    }
}

// ============================================================================
// Kernel B: per window-head attention, fp16 (grid (NWIN,6), 128 thr, 42KB,
// 5 CTAs/SM) — unchanged from round 10.
// ============================================================================
#define H_LDH 40
#define PB_LD 72
#define SC_LD 68
#define AH_SMEM 41984

__global__ void __launch_bounds__(128, 5)
attn_heads()
{
    extern __shared__ char smc[];
    __half* qs = (__half*)smc;
    __half* ks = (__half*)(smc + 5120);
    __half* vs = (__half*)(smc + 10240);
    __half* pb = (__half*)(smc + 15360);
    float*  sc = (float*)(smc + 24576);

    const int tid  = threadIdx.x;
    const int wid  = tid >> 5;
    const int lane = tid & 31;
    const int win  = blockIdx.x;
    const int h    = blockIdx.y;

    {
        const __half* base = g_qkvh + (size_t)win * 49 * 576 + h * 32;
        for (int idx = tid; idx < 3 * 49 * 4; idx += 128) {
            int m = idx / 196, rem = idx - m * 196;
            int r = rem >> 2, c8 = rem & 3;
            float4 v = *(const float4*)(base + (size_t)r * 576 + m * 192 + c8 * 8);
            __half* dst = (m == 0 ? qs : (m == 1 ? ks : vs));
            *(float4*)(dst + r * H_LDH + c8 * 8) = v;
        }
        float4 z = make_float4(0.f, 0.f, 0.f, 0.f);
        for (int idx = tid; idx < 3 * 15 * 4; idx += 128) {
            int m = idx / 60, rem = idx - m * 60;
            int r = 49 + (rem >> 2), c8 = rem & 3;
            __half* dst = (m == 0 ? qs : (m == 1 ? ks : vs));
            *(float4*)(dst + r * H_LDH + c8 * 8) = z;
        }
        for (int idx = tid; idx < 576; idx += 128)
            *(float4*)(pb + idx * 8) = z;
    }
    __syncthreads();

    {
        FragAh af[2];
#pragma unroll
        for (int k = 0; k < 2; k++)
            wmma::load_matrix_sync(af[k], qs + wid * 16 * H_LDH + k * 16, H_LDH);
#pragma unroll
        for (int ct = 0; ct < 4; ct++) {
            FragCf acc; wmma::fill_fragment(acc, 0.f);
#pragma unroll
            for (int k = 0; k < 2; k++) {
                FragBTh bf; wmma::load_matrix_sync(bf, ks + ct * 16 * H_LDH + k * 16, H_LDH);
                wmma::mma_sync(acc, af[k], bf, acc);
            }
            wmma::store_matrix_sync(sc + wid * 16 * SC_LD + ct * 16, acc, SC_LD, wmma::mem_row_major);
        }
    }
    __syncthreads();

    {
        const float* bh = g_bias + h * 2401;
        for (int r = wid; r < 49; r += 4) {
            float* srow = sc + r * SC_LD;
            int j0 = lane, j1 = lane + 32;
            float v0 = srow[j0] + bh[r * 49 + j0];
            float v1 = (j1 < 49) ? srow[j1] + bh[r * 49 + j1] : -1e30f;
            float m = fmaxf(v0, v1);
#pragma unroll
            for (int o = 16; o; o >>= 1) m = fmaxf(m, __shfl_xor_sync(~0u, m, o));
            float e0 = expf(v0 - m);
            float e1 = (j1 < 49) ? expf(v1 - m) : 0.f;
            float s = e0 + e1;
#pragma unroll
            for (int o = 16; o; o >>= 1) s += __shfl_xor_sync(~0u, s, o);
            float inv = 1.f / s;
            __half* prow = pb + r * PB_LD;
            prow[j0] = __float2half_rn(e0 * inv);
            if (j1 < 49) prow[j1] = __float2half_rn(e1 * inv);
        }
    }
    __syncthreads();

    {
        FragAh pf[4];
#pragma unroll
        for (int k = 0; k < 4; k++)
            wmma::load_matrix_sync(pf[k], pb + wid * 16 * PB_LD + k * 16, PB_LD);
#pragma unroll
        for (int ct = 0; ct < 2; ct++) {
            FragCf acc; wmma::fill_fragment(acc, 0.f);
#pragma unroll
            for (int k = 0; k < 4; k++) {
                FragBh bf; wmma::load_matrix_sync(bf, vs + k * 16 * H_LDH + ct * 16, H_LDH);
                wmma::mma_sync(acc, pf[k], bf, acc);
            }
            wmma::store_matrix_sync(sc + wid * 16 * SC_LD + ct * 16, acc, SC_LD, wmma::mem_row_major);
        }
    }
    __syncthreads();

    {
        __half* base = g_attnh + (size_t)win * 49 * DIMC + h * 32;
        for (int idx = tid; idx < 49 * 16; idx += 128) {
            int r = idx >> 4, c2 = idx & 15;
            __half2 h2 = __floats2half2_rn(sc[r * SC_LD + c2 * 2], sc[r * SC_LD + c2 * 2 + 1]);
            *(__half2*)(base + (size_t)r * DIMC + c2 * 2) = h2;
        }
    }
}

// ============================================================================
// Kernel C: proj (fp16) + residual + LN2, 64-token tiles (6272 CTAs, 256 thr,
// 2 CTAs/SM), warp tile 2rt x 3ct (0.83 loads/mma), single 192-col pass.
// smem: xh half[64][200]@0 (25600); st f32[64][196]@25600 (50176). 75776
// ============================================================================
#define PJ_LD 196
#define PROJ_SMEM 75776

__global__ void __launch_bounds__(256, 2)
proj_ln2(const float* __restrict__ x,
         const float* __restrict__ projb,
         const float* __restrict__ ln2w, const float* __restrict__ ln2b)
{
    extern __shared__ char smc[];
    __half* xh = (__half*)smc;
    float*  st = (float*)(smc + 25600);

    const int tid  = threadIdx.x;
    const int wid  = tid >> 5;
    const int lane = tid & 31;
    const int t0   = blockIdx.x * 64;

    // load attn-out (fp16, coalesced)
    {
        const float4* src = (const float4*)(g_attnh + (size_t)t0 * DIMC);
        for (int idx = tid; idx < 64 * 24; idx += 256) {
            int r = idx / 24, c8 = idx - r * 24;
            *(float4*)(xh + r * XH_LD + c8 * 8) = src[idx];
        }
    }
    __syncthreads();

    // proj GEMM fp16: warp tile 2rt x 3ct, 8 warps = 2rtg x 4ctg (12 ct)
    const int rtg = wid & 1;
    const int ctg = wid >> 1;
    {
        FragCf acc[2][3];
#pragma unroll
        for (int i = 0; i < 2; i++)
#pragma unroll
            for (int j = 0; j < 3; j++) wmma::fill_fragment(acc[i][j], 0.f);

        for (int k = 0; k < 12; k++) {
            FragAh af[2];
#pragma unroll
            for (int i = 0; i < 2; i++)
                wmma::load_matrix_sync(af[i], xh + (rtg * 32 + i * 16) * XH_LD + k * 16, XH_LD);
#pragma unroll
            for (int j = 0; j < 3; j++) {
                FragBh bf;
                wmma::load_matrix_sync(bf, g_projw_h + (size_t)k * 16 * 192 + (ctg * 3 + j) * 16, 192);
#pragma unroll
                for (int i = 0; i < 2; i++)
                    wmma::mma_sync(acc[i][j], af[i], bf, acc[i][j]);
            }
        }
#pragma unroll
        for (int i = 0; i < 2; i++)
#pragma unroll
            for (int j = 0; j < 3; j++)
                wmma::store_matrix_sync(st + (rtg * 32 + i * 16) * PJ_LD + (ctg * 3 + j) * 16,
                                        acc[i][j], PJ_LD, wmma::mem_row_major);
    }
    __syncthreads();

    // residual: st += x + projb
    {
        const int r = tid & 63;
        const int t = t0 + r;
        const int win = t / 49, pos = t - win * 49;
        const int b = win >> 10, wh = (win >> 5) & 31, ww = win & 31;
        const int pi = pos / 7;
        const float* src = x + (size_t)b * DIMC * HWSQ + (wh * 7 + pi) * HWI + (ww * 7 + pos - pi * 7);
        for (int c = tid >> 6; c < DIMC; c += 4)
            st[r * PJ_LD + c] += src[(size_t)c * HWSQ] + projb[c];
    }
    __syncthreads();

    // LN2 + write h1 (fp32) / h1n (bf16)
    for (int r = wid; r < 64; r += 8) {
        float v[6]; float s = 0.f;
#pragma unroll
        for (int q = 0; q < 6; q++) { v[q] = st[r * PJ_LD + lane + q * 32]; s += v[q]; }
#pragma unroll
        for (int o = 16; o; o >>= 1) s += __shfl_xor_sync(~0u, s, o);
        float mu = s * (1.f / 192.f);
        float vs = 0.f;
#pragma unroll
        for (int q = 0; q < 6; q++) { float d = v[q] - mu; vs += d * d; }
#pragma unroll
        for (int o = 16; o; o >>= 1) vs += __shfl_xor_sync(~0u, vs, o);
        float rs = rsqrtf(vs * (1.f / 192.f) + 1e-5f);
        size_t base = (size_t)(t0 + r) * DIMC;
#pragma unroll
        for (int q = 0; q < 6; q++) {
            int c = lane + q * 32;
            g_h1 [base + c] = v[q];
            g_h1n[base + c] = __float2bfloat16((v[q] - mu) * rs * ln2w[c] + ln2b[c]);
        }
    }
}

// ============================================================================
// Kernel D: MLP, bf16, 64-token tiles (6272 CTAs, 256 thr, 2 CTAs/SM),
// warp tile 2rt x 3ct everywhere (0.83 loads/mma). GEMM2 accumulators
// acc2[2][3] register-resident across the 4 K-chunks.
// smem: as bf16[64][200]@0 (25600); mid f32[64][196]@25600 (50176);
//       midb bf16[64][200]@75776 (25600); total 101376
// ============================================================================
#define AS_LD 200
#define MD_LD 196
#define MLP_SMEM 101376

__global__ void __launch_bounds__(256, 2)
mlp_kernel(const float* __restrict__ fc1b, const float* __restrict__ fc2b,
           float* __restrict__ out)
{
    extern __shared__ char smc[];
    bf16*  as   = (bf16*)smc;
    float* mid  = (float*)(smc + 25600);
    bf16*  midb = (bf16*)(smc + 75776);

    const int tid = threadIdx.x;
    const int wid = tid >> 5;
    const int t0  = blockIdx.x * 64;
    const int rtg = wid & 1;     // rows rtg*32 .. +31
    const int ctg = wid >> 1;    // 0..3: ct tiles ctg*3 .. +2

    {
        const uint4* src = (const uint4*)g_h1n;
        uint4* dst = (uint4*)as;
        for (int idx = tid; idx < 64 * 24; idx += 256) {
            int r = idx / 24, c = idx - r * 24;
            dst[r * 25 + c] = src[(size_t)(t0 + r) * 24 + c];
        }
    }
    __syncthreads();

    FragCf acc2[2][3];
#pragma unroll
    for (int i = 0; i < 2; i++)
#pragma unroll
        for (int j = 0; j < 3; j++) wmma::fill_fragment(acc2[i][j], 0.f);

    for (int chunk = 0; chunk < 4; chunk++) {
        // GEMM1: [64,192] x [192,192] bf16, warp tile 2rt x 3ct
        {
            FragCf acc[2][3];
#pragma unroll
            for (int i = 0; i < 2; i++)
#pragma unroll
                for (int j = 0; j < 3; j++) wmma::fill_fragment(acc[i][j], 0.f);

            for (int k = 0; k < 12; k++) {
                FragAb af[2];
#pragma unroll
                for (int i = 0; i < 2; i++)
                    wmma::load_matrix_sync(af[i], as + (rtg * 32 + i * 16) * AS_LD + k * 16, AS_LD);
#pragma unroll
                for (int j = 0; j < 3; j++) {
                    FragBb bf;
                    wmma::load_matrix_sync(bf, g_fc1w_b + (size_t)k * 16 * 768 + chunk * 192 + (ctg * 3 + j) * 16, 768);
#pragma unroll
                    for (int i = 0; i < 2; i++)
                        wmma::mma_sync(acc[i][j], af[i], bf, acc[i][j]);
                }
            }
#pragma unroll
            for (int i = 0; i < 2; i++)
#pragma unroll
                for (int j = 0; j < 3; j++)
                    wmma::store_matrix_sync(mid + (rtg * 32 + i * 16) * MD_LD + (ctg * 3 + j) * 16,
                                            acc[i][j], MD_LD, wmma::mem_row_major);
        }
        __syncthreads();

        // bias + exact GELU -> midb bf16
        for (int idx = tid; idx < 64 * 192; idx += 256) {
            int r = idx / 192, c = idx - r * 192;
            float v = mid[r * MD_LD + c] + fc1b[chunk * 192 + c];
            midb[r * AS_LD + c] = __float2bfloat16(0.5f * v * (1.f + erff(v * 0.70710678118654752f)));
        }
        __syncthreads();

        // GEMM2 partial: warp tile 2rt x 3ct, register accumulate across chunks
        for (int k = 0; k < 12; k++) {
            FragAb af[2];
#pragma unroll
            for (int i = 0; i < 2; i++)
                wmma::load_matrix_sync(af[i], midb + (rtg * 32 + i * 16) * AS_LD + k * 16, AS_LD);
#pragma unroll
            for (int j = 0; j < 3; j++) {
                FragBb bf;
                wmma::load_matrix_sync(bf, g_fc2w_b + (size_t)(chunk * 192 + k * 16) * 192 + (ctg * 3 + j) * 16, 192);
#pragma unroll
                for (int i = 0; i < 2; i++)
                    wmma::mma_sync(acc2[i][j], af[i], bf, acc2[i][j]);
            }
        }
        __syncthreads();
    }

    // store MLP output
#pragma unroll
    for (int i = 0; i < 2; i++)
#pragma unroll
        for (int j = 0; j < 3; j++)
            wmma::store_matrix_sync(mid + (rtg * 32 + i * 16) * MD_LD + (ctg * 3 + j) * 16,
                                    acc2[i][j], MD_LD, wmma::mem_row_major);
    __syncthreads();

    // residual + bias + scatter to NCHW
    for (int idx = tid; idx < 64 * 192; idx += 256) {
        int r = idx & 63;
        int c = idx >> 6;
        int t = t0 + r;
        int win = t / 49; int pos = t - win * 49;
        int b  = win >> 10;
        int wh = (win >> 5) & 31;
        int ww = win & 31;
        int pi = pos / 7;
        int hh = wh * 7 + pi;
        int wx = ww * 7 + (pos - pi * 7);
        out[((size_t)(b * DIMC + c)) * HWSQ + hh * HWI + wx] =
            mid[r * MD_LD + c] + g_h1[(size_t)t * 192 + c] + fc2b[c];
    }
}

// ============================================================================
extern "C" void kernel_launch(void* const* d_in, const int* in_sizes, int n_in,
                              void* d_out, int out_size)
{
    (void)in_sizes; (void)n_in; (void)out_size;
    const float* x     = (const float*)d_in[0];
    const float* ln1w  = (const float*)d_in[1];
    const float* ln1b  = (const float*)d_in[2];
    const float* qkvw  = (const float*)d_in[3];
    const float* qkvb  = (const float*)d_in[4];
    const float* projw = (const float*)d_in[5];
    const float* projb = (const float*)d_in[6];
    const float* rpb   = (const float*)d_in[7];
    const float* ln2w  = (const float*)d_in[8];
    const float* ln2b  = (const float*)d_in[9];
    const float* fc1w  = (const float*)d_in[10];
    const float* fc1b  = (const float*)d_in[11];
    const float* fc2w  = (const float*)d_in[12];
    const float* fc2b  = (const float*)d_in[13];
    const int*   ridx  = (const int*)  d_in[14];
    float* out = (float*)d_out;

    cudaFuncSetAttribute(qkv_gemm,   cudaFuncAttributeMaxDynamicSharedMemorySize, QKV_SMEM);
    cudaFuncSetAttribute(attn_heads, cudaFuncAttributeMaxDynamicSharedMemorySize, AH_SMEM);
    cudaFuncSetAttribute(proj_ln2,   cudaFuncAttributeMaxDynamicSharedMemorySize, PROJ_SMEM);
    cudaFuncSetAttribute(mlp_kernel, cudaFuncAttributeMaxDynamicSharedMemorySize, MLP_SMEM);

    prelude<<<(PRE_TOT + 511) / 512, 512>>>(qkvw, projw, fc1w, fc2w, rpb, ridx);

    qkv_gemm<<<TTOK / 64, 256, QKV_SMEM>>>(x, ln1w, ln1b, qkvb);

    dim3 ag(NWIN, 6);
    attn_heads<<<ag, 128, AH_SMEM>>>();

    proj_ln2<<<TTOK / 64, 256, PROJ_SMEM>>>(x, projb, ln2w, ln2b);

    mlp_kernel<<<TTOK / 64, 256, MLP_SMEM>>>(fc1b, fc2b, out);
}

// round 13
// speedup vs baseline: 1.4807x; 1.0050x over previous
#include <cuda_runtime.h>
#include <cuda_bf16.h>
#include <cuda_fp16.h>
#include <mma.h>
#include <cmath>
#include <cstdint>

using namespace nvcuda;
typedef __nv_bfloat16 bf16;

// ---------------- problem constants ----------------
#define NWIN   8192
#define TTOK   401408
#define HWI    224
#define HWSQ   50176
#define DIMC   192

// scratch (allocation-free static device arrays)
__device__ __half g_qkvh [(size_t)TTOK * 576];   // QKV (scaled/biased, fp16)
__device__ __half g_attnh[(size_t)TTOK * DIMC];  // attention out (fp16)
__device__ float  g_h1  [(size_t)TTOK * DIMC];   // x + attn branch (fp32)
__device__ __half g_qkvw_h[192 * 576];
__device__ __half g_projw_h[192 * 192];
__device__ bf16   g_fc1w_b [192 * 768];
__device__ bf16   g_fc2w_b [768 * 192];
__device__ float  g_bias   [6 * 49 * 49];

// fp16 fragments (attention path)
typedef wmma::fragment<wmma::matrix_a,16,16,16,__half,wmma::row_major> FragAh;
typedef wmma::fragment<wmma::matrix_b,16,16,16,__half,wmma::row_major> FragBh;
typedef wmma::fragment<wmma::matrix_b,16,16,16,__half,wmma::col_major> FragBTh;
typedef wmma::fragment<wmma::accumulator,16,16,16,float> FragCf;
// bf16 fragments (MLP path)
typedef wmma::fragment<wmma::matrix_a,16,16,16,bf16,wmma::row_major> FragAb;
typedef wmma::fragment<wmma::matrix_b,16,16,16,bf16,wmma::row_major> FragBb;

// ---------------- prelude ----------------
#define W_QKV 110592
#define W_PRJ  36864
#define W_FC1 147456
#define W_FC2 147456
#define N_BIAS 14406
#define PRE_TOT (W_QKV + W_PRJ + W_FC1 + W_FC2 + N_BIAS)

__global__ void prelude(const float* __restrict__ qkvw, const float* __restrict__ projw,
                        const float* __restrict__ fc1w, const float* __restrict__ fc2w,
                        const float* __restrict__ rpb,  const int* __restrict__ relidx)
{
    int i = blockIdx.x * blockDim.x + threadIdx.x;
    if (i < W_QKV) { g_qkvw_h[i] = __float2half_rn(qkvw[i]); return; }
    i -= W_QKV;
    if (i < W_PRJ) { g_projw_h[i] = __float2half_rn(projw[i]); return; }
    i -= W_PRJ;
    if (i < W_FC1) { g_fc1w_b[i] = __float2bfloat16(fc1w[i]); return; }
    i -= W_FC1;
    if (i < W_FC2) { g_fc2w_b[i] = __float2bfloat16(fc2w[i]); return; }
    i -= W_FC2;
    if (i < N_BIAS) {
        int h = i / 2401, rj = i - h * 2401;
        g_bias[i] = rpb[relidx[rj] * 6 + h];
    }
}

// ============================================================================
// Kernel A: batched QKV GEMM, fp16, 64-token tiles (unchanged from round 12)
// ============================================================================
#define XN_LD 196
#define XH_LD 200
#define ST_LD 196
#define QKV_SMEM 75776

__global__ void __launch_bounds__(256, 2)
qkv_gemm(const float* __restrict__ x,
         const float* __restrict__ ln1w, const float* __restrict__ ln1b,
         const float* __restrict__ qkvb)
{
    extern __shared__ char smc[];
    float*  xnf = (float*)smc;
    float*  st  = (float*)smc;                 // overlay (used after LN1)
    __half* xh  = (__half*)(smc + 50176);

    const int tid  = threadIdx.x;
    const int wid  = tid >> 5;
    const int lane = tid & 31;
    const int t0   = blockIdx.x * 64;

    {
        const int r = tid & 63;
        const int t = t0 + r;
        const int win = t / 49, pos = t - win * 49;
        const int b = win >> 10, wh = (win >> 5) & 31, ww = win & 31;
        const int pi = pos / 7;
        const float* src = x + (size_t)b * DIMC * HWSQ + (wh * 7 + pi) * HWI + (ww * 7 + pos - pi * 7);
        for (int c = tid >> 6; c < DIMC; c += 4)
            xnf[r * XN_LD + c] = src[(size_t)c * HWSQ];
    }
    __syncthreads();

    for (int r = wid; r < 64; r += 8) {
        float v[6]; float s = 0.f;
#pragma unroll
        for (int q = 0; q < 6; q++) { v[q] = xnf[r * XN_LD + lane + q * 32]; s += v[q]; }
#pragma unroll
        for (int o = 16; o; o >>= 1) s += __shfl_xor_sync(~0u, s, o);
        float mu = s * (1.f / 192.f);
        float vs = 0.f;
#pragma unroll
        for (int q = 0; q < 6; q++) { float d = v[q] - mu; vs += d * d; }
#pragma unroll
        for (int o = 16; o; o >>= 1) vs += __shfl_xor_sync(~0u, vs, o);
        float rs = rsqrtf(vs * (1.f / 192.f) + 1e-5f);
#pragma unroll
        for (int q = 0; q < 6; q++) {
            int c = lane + q * 32;
            xh[r * XH_LD + c] = __float2half_rn((v[q] - mu) * rs * ln1w[c] + ln1b[c]);
        }
    }
    __syncthreads();

    const int rtg = wid & 1;
    const int ctg = wid >> 1;
    const float scale = 0.17677669529663687f;

    for (int chunk = 0; chunk < 3; chunk++) {
        FragCf acc[2][3];
#pragma unroll
        for (int i = 0; i < 2; i++)
#pragma unroll
            for (int j = 0; j < 3; j++) wmma::fill_fragment(acc[i][j], 0.f);

        for (int k = 0; k < 12; k++) {
            FragAh af[2];
#pragma unroll
            for (int i = 0; i < 2; i++)
                wmma::load_matrix_sync(af[i], xh + (rtg * 32 + i * 16) * XH_LD + k * 16, XH_LD);
#pragma unroll
            for (int j = 0; j < 3; j++) {
                FragBh bf;
                wmma::load_matrix_sync(bf, g_qkvw_h + (size_t)k * 16 * 576 + chunk * 192 + (ctg * 3 + j) * 16, 576);
#pragma unroll
                for (int i = 0; i < 2; i++)
                    wmma::mma_sync(acc[i][j], af[i], bf, acc[i][j]);
            }
        }
#pragma unroll
        for (int i = 0; i < 2; i++)
#pragma unroll
            for (int j = 0; j < 3; j++)
                wmma::store_matrix_sync(st + (rtg * 32 + i * 16) * ST_LD + (ctg * 3 + j) * 16,
                                        acc[i][j], ST_LD, wmma::mem_row_major);
        __syncthreads();

        for (int idx = tid; idx < 64 * 192; idx += 256) {
            int r = idx / 192, cl = idx - r * 192;
            int gc = chunk * 192 + cl;
            float v = st[r * ST_LD + cl] + qkvb[gc];
            if (gc < 192) v *= scale;
            g_qkvh[(size_t)(t0 + r) * 576 + gc] = __float2half_rn(v);
        }
        __syncthreads();
    }
}

// ============================================================================
// Kernel B: per window-head attention, fp16 (unchanged from round 10/12)
// ============================================================================
#define H_LDH 40
#define PB_LD 72
#define SC_LD 68
#define AH_SMEM 41984

__global__ void __launch_bounds__(128, 5)
attn_heads()
{
    extern __shared__ char smc[];
    __half* qs = (__half*)smc;
    __half* ks = (__half*)(smc + 5120);
    __half* vs = (__half*)(smc + 10240);
    __half* pb = (__half*)(smc + 15360);
    float*  sc = (float*)(smc + 24576);

    const int tid  = threadIdx.x;
    const int wid  = tid >> 5;
    const int lane = tid & 31;
    const int win  = blockIdx.x;
    const int h    = blockIdx.y;

    {
        const __half* base = g_qkvh + (size_t)win * 49 * 576 + h * 32;
        for (int idx = tid; idx < 3 * 49 * 4; idx += 128) {
            int m = idx / 196, rem = idx - m * 196;
            int r = rem >> 2, c8 = rem & 3;
            float4 v = *(const float4*)(base + (size_t)r * 576 + m * 192 + c8 * 8);
            __half* dst = (m == 0 ? qs : (m == 1 ? ks : vs));
            *(float4*)(dst + r * H_LDH + c8 * 8) = v;
        }
        float4 z = make_float4(0.f, 0.f, 0.f, 0.f);
        for (int idx = tid; idx < 3 * 15 * 4; idx += 128) {
            int m = idx / 60, rem = idx - m * 60;
            int r = 49 + (rem >> 2), c8 = rem & 3;
            __half* dst = (m == 0 ? qs : (m == 1 ? ks : vs));
            *(float4*)(dst + r * H_LDH + c8 * 8) = z;
        }
        for (int idx = tid; idx < 576; idx += 128)
            *(float4*)(pb + idx * 8) = z;
    }
    __syncthreads();

    {
        FragAh af[2];
#pragma unroll
        for (int k = 0; k < 2; k++)
            wmma::load_matrix_sync(af[k], qs + wid * 16 * H_LDH + k * 16, H_LDH);
#pragma unroll
        for (int ct = 0; ct < 4; ct++) {
            FragCf acc; wmma::fill_fragment(acc, 0.f);
#pragma unroll
            for (int k = 0; k < 2; k++) {
                FragBTh bf; wmma::load_matrix_sync(bf, ks + ct * 16 * H_LDH + k * 16, H_LDH);
                wmma::mma_sync(acc, af[k], bf, acc);
            }
            wmma::store_matrix_sync(sc + wid * 16 * SC_LD + ct * 16, acc, SC_LD, wmma::mem_row_major);
        }
    }
    __syncthreads();

    {
        const float* bh = g_bias + h * 2401;
        for (int r = wid; r < 49; r += 4) {
            float* srow = sc + r * SC_LD;
            int j0 = lane, j1 = lane + 32;
            float v0 = srow[j0] + bh[r * 49 + j0];
            float v1 = (j1 < 49) ? srow[j1] + bh[r * 49 + j1] : -1e30f;
            float m = fmaxf(v0, v1);
#pragma unroll
            for (int o = 16; o; o >>= 1) m = fmaxf(m, __shfl_xor_sync(~0u, m, o));
            float e0 = expf(v0 - m);
            float e1 = (j1 < 49) ? expf(v1 - m) : 0.f;
            float s = e0 + e1;
#pragma unroll
            for (int o = 16; o; o >>= 1) s += __shfl_xor_sync(~0u, s, o);
            float inv = 1.f / s;
            __half* prow = pb + r * PB_LD;
            prow[j0] = __float2half_rn(e0 * inv);
            if (j1 < 49) prow[j1] = __float2half_rn(e1 * inv);
        }
    }
    __syncthreads();

    {
        FragAh pf[4];
#pragma unroll
        for (int k = 0; k < 4; k++)
            wmma::load_matrix_sync(pf[k], pb + wid * 16 * PB_LD + k * 16, PB_LD);
#pragma unroll
        for (int ct = 0; ct < 2; ct++) {
            FragCf acc; wmma::fill_fragment(acc, 0.f);
#pragma unroll
            for (int k = 0; k < 4; k++) {
                FragBh bf; wmma::load_matrix_sync(bf, vs + k * 16 * H_LDH + ct * 16, H_LDH);
                wmma::mma_sync(acc, pf[k], bf, acc);
            }
            wmma::store_matrix_sync(sc + wid * 16 * SC_LD + ct * 16, acc, SC_LD, wmma::mem_row_major);
        }
    }
    __syncthreads();

    {
        __half* base = g_attnh + (size_t)win * 49 * DIMC + h * 32;
        for (int idx = tid; idx < 49 * 16; idx += 128) {
            int r = idx >> 4, c2 = idx & 15;
            __half2 h2 = __floats2half2_rn(sc[r * SC_LD + c2 * 2], sc[r * SC_LD + c2 * 2 + 1]);
            *(__half2*)(base + (size_t)r * DIMC + c2 * 2) = h2;
        }
    }
}

// ============================================================================
// Kernel C (FUSED): proj + residual + LN2 + MLP + out, 64-token tiles
// (6272 CTAs, 256 thr, 2 CTAs/SM).
// smem layout (101376 B):
//   xh  half[64][200] @0      25600  (attn-out / proj A)  -> midb overlays
//   st  f32 [64][196] @25600  50176  (proj out / h1)      -> mid  overlays
//   as  bf16[64][200] @75776  25600  (h1n, alive through MLP)
// h1 parked in g_h1 between LN2 and the final epilogue.
// ============================================================================
#define PJ_LD 196
#define MD_LD 196
#define AS_LD 200
#define TAIL_SMEM 101376

__global__ void __launch_bounds__(256, 2)
tail_kernel(const float* __restrict__ x,
            const float* __restrict__ projb,
            const float* __restrict__ ln2w, const float* __restrict__ ln2b,
            const float* __restrict__ fc1b, const float* __restrict__ fc2b,
            float* __restrict__ out)
{
    extern __shared__ char smc[];
    __half* xh   = (__half*)smc;
    float*  st   = (float*)(smc + 25600);
    bf16*   as   = (bf16*)(smc + 75776);
    float*  mid  = (float*)(smc + 25600);   // overlays st (after LN2)
    bf16*   midb = (bf16*)smc;              // overlays xh (after proj GEMM)

    const int tid  = threadIdx.x;
    const int wid  = tid >> 5;
    const int lane = tid & 31;
    const int t0   = blockIdx.x * 64;
    const int rtg  = wid & 1;
    const int ctg  = wid >> 1;

    // ---- load attn-out (fp16, coalesced) ----
    {
        const float4* src = (const float4*)(g_attnh + (size_t)t0 * DIMC);
        for (int idx = tid; idx < 64 * 24; idx += 256) {
            int r = idx / 24, c8 = idx - r * 24;
            *(float4*)(xh + r * XH_LD + c8 * 8) = src[idx];
        }
    }
    __syncthreads();

    // ---- proj GEMM fp16: warp tile 2rt x 3ct -> st ----
    {
        FragCf acc[2][3];
#pragma unroll
        for (int i = 0; i < 2; i++)
#pragma unroll
            for (int j = 0; j < 3; j++) wmma::fill_fragment(acc[i][j], 0.f);

        for (int k = 0; k < 12; k++) {
            FragAh af[2];
#pragma unroll
            for (int i = 0; i < 2; i++)
                wmma::load_matrix_sync(af[i], xh + (rtg * 32 + i * 16) * XH_LD + k * 16, XH_LD);
#pragma unroll
            for (int j = 0; j < 3; j++) {
                FragBh bf;
                wmma::load_matrix_sync(bf, g_projw_h + (size_t)k * 16 * 192 + (ctg * 3 + j) * 16, 192);
#pragma unroll
                for (int i = 0; i < 2; i++)
                    wmma::mma_sync(acc[i][j], af[i], bf, acc[i][j]);
            }
        }
#pragma unroll
        for (int i = 0; i < 2; i++)
#pragma unroll
            for (int j = 0; j < 3; j++)
                wmma::store_matrix_sync(st + (rtg * 32 + i * 16) * PJ_LD + (ctg * 3 + j) * 16,
                                        acc[i][j], PJ_LD, wmma::mem_row_major);
    }
    __syncthreads();

    // ---- residual: st += x + projb ----
    {
        const int r = tid & 63;
        const int t = t0 + r;
        const int win = t / 49, pos = t - win * 49;
        const int b = win >> 10, wh = (win >> 5) & 31, ww = win & 31;
        const int pi = pos / 7;
        const float* src = x + (size_t)b * DIMC * HWSQ + (wh * 7 + pi) * HWI + (ww * 7 + pos - pi * 7);
        for (int c = tid >> 6; c < DIMC; c += 4)
            st[r * PJ_LD + c] += src[(size_t)c * HWSQ] + projb[c];
    }
    __syncthreads();

    // ---- LN2: h1 -> g_h1 (global), h1n -> as (smem bf16) ----
    for (int r = wid; r < 64; r += 8) {
        float v[6]; float s = 0.f;
#pragma unroll
        for (int q = 0; q < 6; q++) { v[q] = st[r * PJ_LD + lane + q * 32]; s += v[q]; }
#pragma unroll
        for (int o = 16; o; o >>= 1) s += __shfl_xor_sync(~0u, s, o);
        float mu = s * (1.f / 192.f);
        float vs = 0.f;
#pragma unroll
        for (int q = 0; q < 6; q++) { float d = v[q] - mu; vs += d * d; }
#pragma unroll
        for (int o = 16; o; o >>= 1) vs += __shfl_xor_sync(~0u, vs, o);
        float rs = rsqrtf(vs * (1.f / 192.f) + 1e-5f);
        size_t base = (size_t)(t0 + r) * DIMC;
#pragma unroll
        for (int q = 0; q < 6; q++) {
            int c = lane + q * 32;
            g_h1[base + c] = v[q];
            as[r * AS_LD + c] = __float2bfloat16((v[q] - mu) * rs * ln2w[c] + ln2b[c]);
        }
    }
    __syncthreads();   // st & xh now dead -> mid/midb overlays valid

    // ---- MLP: 4 K-chunks of 192, GEMM2 register-resident ----
    FragCf acc2[2][3];
#pragma unroll
    for (int i = 0; i < 2; i++)
#pragma unroll
        for (int j = 0; j < 3; j++) wmma::fill_fragment(acc2[i][j], 0.f);

    for (int chunk = 0; chunk < 4; chunk++) {
        // GEMM1: [64,192] x [192,192] bf16, warp tile 2rt x 3ct -> mid
        {
            FragCf acc[2][3];
#pragma unroll
            for (int i = 0; i < 2; i++)
#pragma unroll
                for (int j = 0; j < 3; j++) wmma::fill_fragment(acc[i][j], 0.f);

            for (int k = 0; k < 12; k++) {
                FragAb af[2];
#pragma unroll
                for (int i = 0; i < 2; i++)
                    wmma::load_matrix_sync(af[i], as + (rtg * 32 + i * 16) * AS_LD + k * 16, AS_LD);
#pragma unroll
                for (int j = 0; j < 3; j++) {
                    FragBb bf;
                    wmma::load_matrix_sync(bf, g_fc1w_b + (size_t)k * 16 * 768 + chunk * 192 + (ctg * 3 + j) * 16, 768);
#pragma unroll
                    for (int i = 0; i < 2; i++)
                        wmma::mma_sync(acc[i][j], af[i], bf, acc[i][j]);
                }
            }
#pragma unroll
            for (int i = 0; i < 2; i++)
#pragma unroll
                for (int j = 0; j < 3; j++)
                    wmma::store_matrix_sync(mid + (rtg * 32 + i * 16) * MD_LD + (ctg * 3 + j) * 16,
                                            acc[i][j], MD_LD, wmma::mem_row_major);
        }
        __syncthreads();

        // bias + exact GELU -> midb bf16
        for (int idx = tid; idx < 64 * 192; idx += 256) {
            int r = idx / 192, c = idx - r * 192;
            float v = mid[r * MD_LD + c] + fc1b[chunk * 192 + c];
            midb[r * AS_LD + c] = __float2bfloat16(0.5f * v * (1.f + erff(v * 0.70710678118654752f)));
        }
        __syncthreads();

        // GEMM2 partial: warp tile 2rt x 3ct, register accumulate across chunks
        for (int k = 0; k < 12; k++) {
            FragAb af[2];
#pragma unroll
            for (int i = 0; i < 2; i++)
                wmma::load_matrix_sync(af[i], midb + (rtg * 32 + i * 16) * AS_LD + k * 16, AS_LD);
#pragma unroll
            for (int j = 0; j < 3; j++) {
                FragBb bf;
                wmma::load_matrix_sync(bf, g_fc2w_b + (size_t)(chunk * 192 + k * 16) * 192 + (ctg * 3 + j) * 16, 192);
#pragma unroll
                for (int i = 0; i < 2; i++)
                    wmma::mma_sync(acc2[i][j], af[i], bf, acc2[i][j]);
            }
        }
        __syncthreads();
    }

    // ---- store MLP output -> mid ----
#pragma unroll
    for (int i = 0; i < 2; i++)
#pragma unroll
        for (int j = 0; j < 3; j++)
            wmma::store_matrix_sync(mid + (rtg * 32 + i * 16) * MD_LD + (ctg * 3 + j) * 16,
                                    acc2[i][j], MD_LD, wmma::mem_row_major);
    __syncthreads();

    // ---- final: out = mid + h1 + fc2b, scatter to NCHW ----
    for (int idx = tid; idx < 64 * 192; idx += 256) {
        int r = idx & 63;
        int c = idx >> 6;
        int t = t0 + r;
        int win = t / 49; int pos = t - win * 49;
        int b  = win >> 10;
        int wh = (win >> 5) & 31;
        int ww = win & 31;
        int pi = pos / 7;
        int hh = wh * 7 + pi;
        int wx = ww * 7 + (pos - pi * 7);
        out[((size_t)(b * DIMC + c)) * HWSQ + hh * HWI + wx] =
            mid[r * MD_LD + c] + g_h1[(size_t)t * DIMC + c] + fc2b[c];
    }
}

// ============================================================================
extern "C" void kernel_launch(void* const* d_in, const int* in_sizes, int n_in,
                              void* d_out, int out_size)
{
    (void)in_sizes; (void)n_in; (void)out_size;
    const float* x     = (const float*)d_in[0];
    const float* ln1w  = (const float*)d_in[1];
    const float* ln1b  = (const float*)d_in[2];
    const float* qkvw  = (const float*)d_in[3];
    const float* qkvb  = (const float*)d_in[4];
    const float* projw = (const float*)d_in[5];
    const float* projb = (const float*)d_in[6];
    const float* rpb   = (const float*)d_in[7];
    const float* ln2w  = (const float*)d_in[8];
    const float* ln2b  = (const float*)d_in[9];
    const float* fc1w  = (const float*)d_in[10];
    const float* fc1b  = (const float*)d_in[11];
    const float* fc2w  = (const float*)d_in[12];
    const float* fc2b  = (const float*)d_in[13];
    const int*   ridx  = (const int*)  d_in[14];
    float* out = (float*)d_out;

    cudaFuncSetAttribute(qkv_gemm,    cudaFuncAttributeMaxDynamicSharedMemorySize, QKV_SMEM);
    cudaFuncSetAttribute(attn_heads,  cudaFuncAttributeMaxDynamicSharedMemorySize, AH_SMEM);
    cudaFuncSetAttribute(tail_kernel, cudaFuncAttributeMaxDynamicSharedMemorySize, TAIL_SMEM);

    prelude<<<(PRE_TOT + 511) / 512, 512>>>(qkvw, projw, fc1w, fc2w, rpb, ridx);

    qkv_gemm<<<TTOK / 64, 256, QKV_SMEM>>>(x, ln1w, ln1b, qkvb);

    dim3 ag(NWIN, 6);
    attn_heads<<<ag, 128, AH_SMEM>>>();

    tail_kernel<<<TTOK / 64, 256, TAIL_SMEM>>>(x, projb, ln2w, ln2b, fc1b, fc2b, out);
}

// round 14
// speedup vs baseline: 1.6464x; 1.1119x over previous
#include <cuda_runtime.h>
#include <cuda_bf16.h>
#include <cuda_fp16.h>
#include <mma.h>
#include <cmath>
#include <cstdint>

using namespace nvcuda;
typedef __nv_bfloat16 bf16;

// ---------------- problem constants ----------------
#define NWIN   8192
#define TTOK   401408
#define HWI    224
#define HWSQ   50176
#define DIMC   192

// scratch (allocation-free static device arrays)
__device__ __half g_qkvh [(size_t)TTOK * 576];   // QKV (scaled/biased, fp16)
__device__ __half g_attnh[(size_t)TTOK * DIMC];  // attention out (fp16)
__device__ float  g_h1  [(size_t)TTOK * DIMC];   // x + attn branch (fp32)
__device__ __half g_qkvw_h[192 * 576];
__device__ __half g_projw_h[192 * 192];
__device__ bf16   g_fc1w_b [192 * 768];
__device__ bf16   g_fc2w_b [768 * 192];
__device__ float  g_bias   [6 * 49 * 49];

// fp16 fragments (attention path)
typedef wmma::fragment<wmma::matrix_a,16,16,16,__half,wmma::row_major> FragAh;
typedef wmma::fragment<wmma::matrix_b,16,16,16,__half,wmma::row_major> FragBh;
typedef wmma::fragment<wmma::matrix_b,16,16,16,__half,wmma::col_major> FragBTh;
typedef wmma::fragment<wmma::accumulator,16,16,16,float> FragCf;
// bf16 fragments (MLP path)
typedef wmma::fragment<wmma::matrix_a,16,16,16,bf16,wmma::row_major> FragAb;
typedef wmma::fragment<wmma::matrix_b,16,16,16,bf16,wmma::row_major> FragBb;

// ---------------- prelude ----------------
#define W_QKV 110592
#define W_PRJ  36864
#define W_FC1 147456
#define W_FC2 147456
#define N_BIAS 14406
#define PRE_TOT (W_QKV + W_PRJ + W_FC1 + W_FC2 + N_BIAS)

__global__ void prelude(const float* __restrict__ qkvw, const float* __restrict__ projw,
                        const float* __restrict__ fc1w, const float* __restrict__ fc2w,
                        const float* __restrict__ rpb,  const int* __restrict__ relidx)
{
    int i = blockIdx.x * blockDim.x + threadIdx.x;
    if (i < W_QKV) { g_qkvw_h[i] = __float2half_rn(qkvw[i]); return; }
    i -= W_QKV;
    if (i < W_PRJ) { g_projw_h[i] = __float2half_rn(projw[i]); return; }
    i -= W_PRJ;
    if (i < W_FC1) { g_fc1w_b[i] = __float2bfloat16(fc1w[i]); return; }
    i -= W_FC1;
    if (i < W_FC2) { g_fc2w_b[i] = __float2bfloat16(fc2w[i]); return; }
    i -= W_FC2;
    if (i < N_BIAS) {
        int h = i / 2401, rj = i - h * 2401;
        g_bias[i] = rpb[relidx[rj] * 6 + h];
    }
}

// ============================================================================
// Kernel A: batched QKV GEMM, fp16, 64-token tiles (vectorized epilogue)
// ============================================================================
#define XN_LD 196
#define XH_LD 200
#define ST_LD 196
#define QKV_SMEM 75776

__global__ void __launch_bounds__(256, 2)
qkv_gemm(const float* __restrict__ x,
         const float* __restrict__ ln1w, const float* __restrict__ ln1b,
         const float* __restrict__ qkvb)
{
    extern __shared__ char smc[];
    float*  xnf = (float*)smc;
    float*  st  = (float*)smc;                 // overlay (used after LN1)
    __half* xh  = (__half*)(smc + 50176);

    const int tid  = threadIdx.x;
    const int wid  = tid >> 5;
    const int lane = tid & 31;
    const int t0   = blockIdx.x * 64;

    {
        const int r = tid & 63;
        const int t = t0 + r;
        const int win = t / 49, pos = t - win * 49;
        const int b = win >> 10, wh = (win >> 5) & 31, ww = win & 31;
        const int pi = pos / 7;
        const float* src = x + (size_t)b * DIMC * HWSQ + (wh * 7 + pi) * HWI + (ww * 7 + pos - pi * 7);
        for (int c = tid >> 6; c < DIMC; c += 4)
            xnf[r * XN_LD + c] = src[(size_t)c * HWSQ];
    }
    __syncthreads();

    for (int r = wid; r < 64; r += 8) {
        float v[6]; float s = 0.f;
#pragma unroll
        for (int q = 0; q < 6; q++) { v[q] = xnf[r * XN_LD + lane + q * 32]; s += v[q]; }
#pragma unroll
        for (int o = 16; o; o >>= 1) s += __shfl_xor_sync(~0u, s, o);
        float mu = s * (1.f / 192.f);
        float vs = 0.f;
#pragma unroll
        for (int q = 0; q < 6; q++) { float d = v[q] - mu; vs += d * d; }
#pragma unroll
        for (int o = 16; o; o >>= 1) vs += __shfl_xor_sync(~0u, vs, o);
        float rs = rsqrtf(vs * (1.f / 192.f) + 1e-5f);
#pragma unroll
        for (int q = 0; q < 6; q++) {
            int c = lane + q * 32;
            xh[r * XH_LD + c] = __float2half_rn((v[q] - mu) * rs * ln1w[c] + ln1b[c]);
        }
    }
    __syncthreads();

    const int rtg = wid & 1;
    const int ctg = wid >> 1;
    const float scale = 0.17677669529663687f;

    for (int chunk = 0; chunk < 3; chunk++) {
        FragCf acc[2][3];
#pragma unroll
        for (int i = 0; i < 2; i++)
#pragma unroll
            for (int j = 0; j < 3; j++) wmma::fill_fragment(acc[i][j], 0.f);

        for (int k = 0; k < 12; k++) {
            FragAh af[2];
#pragma unroll
            for (int i = 0; i < 2; i++)
                wmma::load_matrix_sync(af[i], xh + (rtg * 32 + i * 16) * XH_LD + k * 16, XH_LD);
#pragma unroll
            for (int j = 0; j < 3; j++) {
                FragBh bf;
                wmma::load_matrix_sync(bf, g_qkvw_h + (size_t)k * 16 * 576 + chunk * 192 + (ctg * 3 + j) * 16, 576);
#pragma unroll
                for (int i = 0; i < 2; i++)
                    wmma::mma_sync(acc[i][j], af[i], bf, acc[i][j]);
            }
        }
#pragma unroll
        for (int i = 0; i < 2; i++)
#pragma unroll
            for (int j = 0; j < 3; j++)
                wmma::store_matrix_sync(st + (rtg * 32 + i * 16) * ST_LD + (ctg * 3 + j) * 16,
                                        acc[i][j], ST_LD, wmma::mem_row_major);
        __syncthreads();

        // epilogue (vectorized x4): bias, q-scale (chunk-uniform), fp16 round
        {
            const float sc = (chunk == 0) ? scale : 1.f;
            for (int idx = tid; idx < 64 * 48; idx += 256) {
                int r = idx / 48, c4 = (idx - r * 48) * 4;
                int gc = chunk * 192 + c4;
                float4 v  = *(const float4*)(st + r * ST_LD + c4);
                float4 bb = *(const float4*)(qkvb + gc);
                __half2 h0 = __floats2half2_rn((v.x + bb.x) * sc, (v.y + bb.y) * sc);
                __half2 h1 = __floats2half2_rn((v.z + bb.z) * sc, (v.w + bb.w) * sc);
                uint2 u; u.x = *(uint32_t*)&h0; u.y = *(uint32_t*)&h1;
                *(uint2*)(g_qkvh + (size_t)(t0 + r) * 576 + gc) = u;
            }
        }
        __syncthreads();
    }
}

// ============================================================================
// Kernel B: per window-head attention, fp16 (unchanged from round 10/12)
// ============================================================================
#define H_LDH 40
#define PB_LD 72
#define SC_LD 68
#define AH_SMEM 41984

__global__ void __launch_bounds__(128, 5)
attn_heads()
{
    extern __shared__ char smc[];
    __half* qs = (__half*)smc;
    __half* ks = (__half*)(smc + 5120);
    __half* vs = (__half*)(smc + 10240);
    __half* pb = (__half*)(smc + 15360);
    float*  sc = (float*)(smc + 24576);

    const int tid  = threadIdx.x;
    const int wid  = tid >> 5;
    const int lane = tid & 31;
    const int win  = blockIdx.x;
    const int h    = blockIdx.y;

    {
        const __half* base = g_qkvh + (size_t)win * 49 * 576 + h * 32;
        for (int idx = tid; idx < 3 * 49 * 4; idx += 128) {
            int m = idx / 196, rem = idx - m * 196;
            int r = rem >> 2, c8 = rem & 3;
            float4 v = *(const float4*)(base + (size_t)r * 576 + m * 192 + c8 * 8);
            __half* dst = (m == 0 ? qs : (m == 1 ? ks : vs));
            *(float4*)(dst + r * H_LDH + c8 * 8) = v;
        }
        float4 z = make_float4(0.f, 0.f, 0.f, 0.f);
        for (int idx = tid; idx < 3 * 15 * 4; idx += 128) {
            int m = idx / 60, rem = idx - m * 60;
            int r = 49 + (rem >> 2), c8 = rem & 3;
            __half* dst = (m == 0 ? qs : (m == 1 ? ks : vs));
            *(float4*)(dst + r * H_LDH + c8 * 8) = z;
        }
        for (int idx = tid; idx < 576; idx += 128)
            *(float4*)(pb + idx * 8) = z;
    }
    __syncthreads();

    {
        FragAh af[2];
#pragma unroll
        for (int k = 0; k < 2; k++)
            wmma::load_matrix_sync(af[k], qs + wid * 16 * H_LDH + k * 16, H_LDH);
#pragma unroll
        for (int ct = 0; ct < 4; ct++) {
            FragCf acc; wmma::fill_fragment(acc, 0.f);
#pragma unroll
            for (int k = 0; k < 2; k++) {
                FragBTh bf; wmma::load_matrix_sync(bf, ks + ct * 16 * H_LDH + k * 16, H_LDH);
                wmma::mma_sync(acc, af[k], bf, acc);
            }
            wmma::store_matrix_sync(sc + wid * 16 * SC_LD + ct * 16, acc, SC_LD, wmma::mem_row_major);
        }
    }
    __syncthreads();

    {
        const float* bh = g_bias + h * 2401;
        for (int r = wid; r < 49; r += 4) {
            float* srow = sc + r * SC_LD;
            int j0 = lane, j1 = lane + 32;
            float v0 = srow[j0] + bh[r * 49 + j0];
            float v1 = (j1 < 49) ? srow[j1] + bh[r * 49 + j1] : -1e30f;
            float m = fmaxf(v0, v1);
#pragma unroll
            for (int o = 16; o; o >>= 1) m = fmaxf(m, __shfl_xor_sync(~0u, m, o));
            float e0 = expf(v0 - m);
            float e1 = (j1 < 49) ? expf(v1 - m) : 0.f;
            float s = e0 + e1;
#pragma unroll
            for (int o = 16; o; o >>= 1) s += __shfl_xor_sync(~0u, s, o);
            float inv = 1.f / s;
            __half* prow = pb + r * PB_LD;
            prow[j0] = __float2half_rn(e0 * inv);
            if (j1 < 49) prow[j1] = __float2half_rn(e1 * inv);
        }
    }
    __syncthreads();

    {
        FragAh pf[4];
#pragma unroll
        for (int k = 0; k < 4; k++)
            wmma::load_matrix_sync(pf[k], pb + wid * 16 * PB_LD + k * 16, PB_LD);
#pragma unroll
        for (int ct = 0; ct < 2; ct++) {
            FragCf acc; wmma::fill_fragment(acc, 0.f);
#pragma unroll
            for (int k = 0; k < 4; k++) {
                FragBh bf; wmma::load_matrix_sync(bf, vs + k * 16 * H_LDH + ct * 16, H_LDH);
                wmma::mma_sync(acc, pf[k], bf, acc);
            }
            wmma::store_matrix_sync(sc + wid * 16 * SC_LD + ct * 16, acc, SC_LD, wmma::mem_row_major);
        }
    }
    __syncthreads();

    {
        __half* base = g_attnh + (size_t)win * 49 * DIMC + h * 32;
        for (int idx = tid; idx < 49 * 16; idx += 128) {
            int r = idx >> 4, c2 = idx & 15;
            __half2 h2 = __floats2half2_rn(sc[r * SC_LD + c2 * 2], sc[r * SC_LD + c2 * 2 + 1]);
            *(__half2*)(base + (size_t)r * DIMC + c2 * 2) = h2;
        }
    }
}

// ============================================================================
// Kernel C (FUSED): proj + residual + LN2 + MLP + out, 64-token tiles.
// Vectorized epilogues; final epilogue split into coalesced 2-pass.
// smem layout (101376 B): xh@0 (25600) -> midb overlays; st@25600 (50176)
// -> mid overlays; as@75776 (25600).
// ============================================================================
#define PJ_LD 196
#define MD_LD 196
#define AS_LD 200
#define TAIL_SMEM 101376

__global__ void __launch_bounds__(256, 2)
tail_kernel(const float* __restrict__ x,
            const float* __restrict__ projb,
            const float* __restrict__ ln2w, const float* __restrict__ ln2b,
            const float* __restrict__ fc1b, const float* __restrict__ fc2b,
            float* __restrict__ out)
{
    extern __shared__ char smc[];
    __half* xh   = (__half*)smc;
    float*  st   = (float*)(smc + 25600);
    bf16*   as   = (bf16*)(smc + 75776);
    float*  mid  = (float*)(smc + 25600);   // overlays st (after LN2)
    bf16*   midb = (bf16*)smc;              // overlays xh (after proj GEMM)

    const int tid  = threadIdx.x;
    const int wid  = tid >> 5;
    const int lane = tid & 31;
    const int t0   = blockIdx.x * 64;
    const int rtg  = wid & 1;
    const int ctg  = wid >> 1;

    // ---- load attn-out (fp16, coalesced) ----
    {
        const float4* src = (const float4*)(g_attnh + (size_t)t0 * DIMC);
        for (int idx = tid; idx < 64 * 24; idx += 256) {
            int r = idx / 24, c8 = idx - r * 24;
            *(float4*)(xh + r * XH_LD + c8 * 8) = src[idx];
        }
    }
    __syncthreads();

    // ---- proj GEMM fp16: warp tile 2rt x 3ct -> st ----
    {
        FragCf acc[2][3];
#pragma unroll
        for (int i = 0; i < 2; i++)
#pragma unroll
            for (int j = 0; j < 3; j++) wmma::fill_fragment(acc[i][j], 0.f);

        for (int k = 0; k < 12; k++) {
            FragAh af[2];
#pragma unroll
            for (int i = 0; i < 2; i++)
                wmma::load_matrix_sync(af[i], xh + (rtg * 32 + i * 16) * XH_LD + k * 16, XH_LD);
#pragma unroll
            for (int j = 0; j < 3; j++) {
                FragBh bf;
                wmma::load_matrix_sync(bf, g_projw_h + (size_t)k * 16 * 192 + (ctg * 3 + j) * 16, 192);
#pragma unroll
                for (int i = 0; i < 2; i++)
                    wmma::mma_sync(acc[i][j], af[i], bf, acc[i][j]);
            }
        }
#pragma unroll
        for (int i = 0; i < 2; i++)
#pragma unroll
            for (int j = 0; j < 3; j++)
                wmma::store_matrix_sync(st + (rtg * 32 + i * 16) * PJ_LD + (ctg * 3 + j) * 16,
                                        acc[i][j], PJ_LD, wmma::mem_row_major);
    }
    __syncthreads();

    // ---- residual: st += x + projb ----
    {
        const int r = tid & 63;
        const int t = t0 + r;
        const int win = t / 49, pos = t - win * 49;
        const int b = win >> 10, wh = (win >> 5) & 31, ww = win & 31;
        const int pi = pos / 7;
        const float* src = x + (size_t)b * DIMC * HWSQ + (wh * 7 + pi) * HWI + (ww * 7 + pos - pi * 7);
        for (int c = tid >> 6; c < DIMC; c += 4)
            st[r * PJ_LD + c] += src[(size_t)c * HWSQ] + projb[c];
    }
    __syncthreads();

    // ---- LN2: h1 -> g_h1 (global), h1n -> as (smem bf16) ----
    for (int r = wid; r < 64; r += 8) {
        float v[6]; float s = 0.f;
#pragma unroll
        for (int q = 0; q < 6; q++) { v[q] = st[r * PJ_LD + lane + q * 32]; s += v[q]; }
#pragma unroll
        for (int o = 16; o; o >>= 1) s += __shfl_xor_sync(~0u, s, o);
        float mu = s * (1.f / 192.f);
        float vs = 0.f;
#pragma unroll
        for (int q = 0; q < 6; q++) { float d = v[q] - mu; vs += d * d; }
#pragma unroll
        for (int o = 16; o; o >>= 1) vs += __shfl_xor_sync(~0u, vs, o);
        float rs = rsqrtf(vs * (1.f / 192.f) + 1e-5f);
        size_t base = (size_t)(t0 + r) * DIMC;
#pragma unroll
        for (int q = 0; q < 6; q++) {
            int c = lane + q * 32;
            g_h1[base + c] = v[q];
            as[r * AS_LD + c] = __float2bfloat16((v[q] - mu) * rs * ln2w[c] + ln2b[c]);
        }
    }
    __syncthreads();   // st & xh now dead -> mid/midb overlays valid

    // ---- MLP: 4 K-chunks of 192, GEMM2 register-resident ----
    FragCf acc2[2][3];
#pragma unroll
    for (int i = 0; i < 2; i++)
#pragma unroll
        for (int j = 0; j < 3; j++) wmma::fill_fragment(acc2[i][j], 0.f);

    for (int chunk = 0; chunk < 4; chunk++) {
        // GEMM1: [64,192] x [192,192] bf16, warp tile 2rt x 3ct -> mid
        {
            FragCf acc[2][3];
#pragma unroll
            for (int i = 0; i < 2; i++)
#pragma unroll
                for (int j = 0; j < 3; j++) wmma::fill_fragment(acc[i][j], 0.f);

            for (int k = 0; k < 12; k++) {
                FragAb af[2];
#pragma unroll
                for (int i = 0; i < 2; i++)
                    wmma::load_matrix_sync(af[i], as + (rtg * 32 + i * 16) * AS_LD + k * 16, AS_LD);
#pragma unroll
                for (int j = 0; j < 3; j++) {
                    FragBb bf;
                    wmma::load_matrix_sync(bf, g_fc1w_b + (size_t)k * 16 * 768 + chunk * 192 + (ctg * 3 + j) * 16, 768);
#pragma unroll
                    for (int i = 0; i < 2; i++)
                        wmma::mma_sync(acc[i][j], af[i], bf, acc[i][j]);
                }
            }
#pragma unroll
            for (int i = 0; i < 2; i++)
#pragma unroll
                for (int j = 0; j < 3; j++)
                    wmma::store_matrix_sync(mid + (rtg * 32 + i * 16) * MD_LD + (ctg * 3 + j) * 16,
                                            acc[i][j], MD_LD, wmma::mem_row_major);
        }
        __syncthreads();

        // bias + exact GELU -> midb bf16 (vectorized x4)
        for (int idx = tid; idx < 64 * 48; idx += 256) {
            int r = idx / 48, c4 = (idx - r * 48) * 4;
            float4 m  = *(const float4*)(mid + r * MD_LD + c4);
            float4 bb = *(const float4*)(fc1b + chunk * 192 + c4);
            float v0 = m.x + bb.x, v1 = m.y + bb.y, v2 = m.z + bb.z, v3 = m.w + bb.w;
            float g0 = 0.5f * v0 * (1.f + erff(v0 * 0.70710678118654752f));
            float g1 = 0.5f * v1 * (1.f + erff(v1 * 0.70710678118654752f));
            float g2 = 0.5f * v2 * (1.f + erff(v2 * 0.70710678118654752f));
            float g3 = 0.5f * v3 * (1.f + erff(v3 * 0.70710678118654752f));
            __nv_bfloat162 b0 = __floats2bfloat162_rn(g0, g1);
            __nv_bfloat162 b1 = __floats2bfloat162_rn(g2, g3);
            uint2 u; u.x = *(uint32_t*)&b0; u.y = *(uint32_t*)&b1;
            *(uint2*)(midb + r * AS_LD + c4) = u;
        }
        __syncthreads();

        // GEMM2 partial: warp tile 2rt x 3ct, register accumulate across chunks
        for (int k = 0; k < 12; k++) {
            FragAb af[2];
#pragma unroll
            for (int i = 0; i < 2; i++)
                wmma::load_matrix_sync(af[i], midb + (rtg * 32 + i * 16) * AS_LD + k * 16, AS_LD);
#pragma unroll
            for (int j = 0; j < 3; j++) {
                FragBb bf;
                wmma::load_matrix_sync(bf, g_fc2w_b + (size_t)(chunk * 192 + k * 16) * 192 + (ctg * 3 + j) * 16, 192);
#pragma unroll
                for (int i = 0; i < 2; i++)
                    wmma::mma_sync(acc2[i][j], af[i], bf, acc2[i][j]);
            }
        }
        __syncthreads();
    }

    // ---- store MLP output -> mid ----
#pragma unroll
    for (int i = 0; i < 2; i++)
#pragma unroll
        for (int j = 0; j < 3; j++)
            wmma::store_matrix_sync(mid + (rtg * 32 + i * 16) * MD_LD + (ctg * 3 + j) * 16,
                                    acc2[i][j], MD_LD, wmma::mem_row_major);
    __syncthreads();

    // ---- final pass 1 (c-fast, coalesced g_h1 reads, vectorized):
    //      mid = (mid + h1) + fc2b  (same per-element order as before) ----
    for (int idx = tid; idx < 64 * 48; idx += 256) {
        int r = idx / 48, c4 = (idx - r * 48) * 4;
        float4 m  = *(const float4*)(mid + r * MD_LD + c4);
        float4 h  = *(const float4*)(g_h1 + (size_t)(t0 + r) * DIMC + c4);
        float4 bb = *(const float4*)(fc2b + c4);
        m.x = (m.x + h.x) + bb.x;
        m.y = (m.y + h.y) + bb.y;
        m.z = (m.z + h.z) + bb.z;
        m.w = (m.w + h.w) + bb.w;
        *(float4*)(mid + r * MD_LD + c4) = m;
    }
    __syncthreads();

    // ---- final pass 2 (r-fast): coalesced NCHW scatter ----
    for (int idx = tid; idx < 64 * 192; idx += 256) {
        int r = idx & 63;
        int c = idx >> 6;
        int t = t0 + r;
        int win = t / 49; int pos = t - win * 49;
        int b  = win >> 10;
        int wh = (win >> 5) & 31;
        int ww = win & 31;
        int pi = pos / 7;
        int hh = wh * 7 + pi;
        int wx = ww * 7 + (pos - pi * 7);
        out[((size_t)(b * DIMC + c)) * HWSQ + hh * HWI + wx] = mid[r * MD_LD + c];
    }
}

// ============================================================================
extern "C" void kernel_launch(void* const* d_in, const int* in_sizes, int n_in,
                              void* d_out, int out_size)
{
    (void)in_sizes; (void)n_in; (void)out_size;
    const float* x     = (const float*)d_in[0];
    const float* ln1w  = (const float*)d_in[1];
    const float* ln1b  = (const float*)d_in[2];
    const float* qkvw  = (const float*)d_in[3];
    const float* qkvb  = (const float*)d_in[4];
    const float* projw = (const float*)d_in[5];
    const float* projb = (const float*)d_in[6];
    const float* rpb   = (const float*)d_in[7];
    const float* ln2w  = (const float*)d_in[8];
    const float* ln2b  = (const float*)d_in[9];
    const float* fc1w  = (const float*)d_in[10];
    const float* fc1b  = (const float*)d_in[11];
    const float* fc2w  = (const float*)d_in[12];
    const float* fc2b  = (const float*)d_in[13];
    const int*   ridx  = (const int*)  d_in[14];
    float* out = (float*)d_out;

    cudaFuncSetAttribute(qkv_gemm,    cudaFuncAttributeMaxDynamicSharedMemorySize, QKV_SMEM);
    cudaFuncSetAttribute(attn_heads,  cudaFuncAttributeMaxDynamicSharedMemorySize, AH_SMEM);
    cudaFuncSetAttribute(tail_kernel, cudaFuncAttributeMaxDynamicSharedMemorySize, TAIL_SMEM);

    prelude<<<(PRE_TOT + 511) / 512, 512>>>(qkvw, projw, fc1w, fc2w, rpb, ridx);

    qkv_gemm<<<TTOK / 64, 256, QKV_SMEM>>>(x, ln1w, ln1b, qkvb);

    dim3 ag(NWIN, 6);
    attn_heads<<<ag, 128, AH_SMEM>>>();

    tail_kernel<<<TTOK / 64, 256, TAIL_SMEM>>>(x, projb, ln2w, ln2b, fc1b, fc2b, out);
}

// round 15
// speedup vs baseline: 3.0195x; 1.8339x over previous
#include <cuda_runtime.h>
#include <cuda_bf16.h>
#include <cuda_fp16.h>
#include <mma.h>
#include <cmath>
#include <cstdint>

using namespace nvcuda;
typedef __nv_bfloat16 bf16;

// ---------------- problem constants ----------------
#define NWIN   8192
#define TTOK   401408
#define HWI    224
#define HWSQ   50176
#define DIMC   192

// scratch (allocation-free static device arrays)
__device__ __half g_qkvh [(size_t)TTOK * 576];   // QKV (scaled/biased, fp16)
__device__ __half g_attnh[(size_t)TTOK * DIMC];  // attention out (fp16)
__device__ float  g_h1  [(size_t)TTOK * DIMC];   // x + attn branch (fp32)
__device__ float  g_bias [6 * 49 * 49];

// pre-packed B fragments (mma.sync m16n8k16 layout), one uint4 per lane per 16x16 tile
#define N_QKVP  (36 * 12 * 32)
#define N_PROJP (12 * 12 * 32)
#define N_FC1P  (48 * 12 * 32)
#define N_FC2P  (12 * 48 * 32)
__device__ uint4 g_qkvp [N_QKVP];
__device__ uint4 g_projp[N_PROJP];
__device__ uint4 g_fc1p [N_FC1P];
__device__ uint4 g_fc2p [N_FC2P];

// fp16 wmma fragments (attention kernel only)
typedef wmma::fragment<wmma::matrix_a,16,16,16,__half,wmma::row_major> FragAh;
typedef wmma::fragment<wmma::matrix_b,16,16,16,__half,wmma::row_major> FragBh;
typedef wmma::fragment<wmma::matrix_b,16,16,16,__half,wmma::col_major> FragBTh;
typedef wmma::fragment<wmma::accumulator,16,16,16,float> FragCf;

// ---------------- mma.sync helpers ----------------
__device__ __forceinline__ uint32_t smem_u32(const void* p) {
    uint32_t a;
    asm("{ .reg .u64 t; cvta.to.shared.u64 t, %1; cvt.u32.u64 %0, t; }" : "=r"(a) : "l"(p));
    return a;
}
__device__ __forceinline__ void ldsm_x4(uint32_t (&r)[4], uint32_t addr) {
    asm volatile("ldmatrix.sync.aligned.m8n8.x4.shared.b16 {%0,%1,%2,%3}, [%4];"
        : "=r"(r[0]), "=r"(r[1]), "=r"(r[2]), "=r"(r[3]) : "r"(addr));
}
__device__ __forceinline__ void mma_h(float (&c)[4], const uint32_t (&a)[4], uint32_t b0, uint32_t b1) {
    asm volatile("mma.sync.aligned.m16n8k16.row.col.f32.f16.f16.f32 "
        "{%0,%1,%2,%3},{%4,%5,%6,%7},{%8,%9},{%0,%1,%2,%3};"
        : "+f"(c[0]), "+f"(c[1]), "+f"(c[2]), "+f"(c[3])
        : "r"(a[0]), "r"(a[1]), "r"(a[2]), "r"(a[3]), "r"(b0), "r"(b1));
}
__device__ __forceinline__ void mma_b(float (&c)[4], const uint32_t (&a)[4], uint32_t b0, uint32_t b1) {
    asm volatile("mma.sync.aligned.m16n8k16.row.col.f32.bf16.bf16.f32 "
        "{%0,%1,%2,%3},{%4,%5,%6,%7},{%8,%9},{%0,%1,%2,%3};"
        : "+f"(c[0]), "+f"(c[1]), "+f"(c[2]), "+f"(c[3])
        : "r"(a[0]), "r"(a[1]), "r"(a[2]), "r"(a[3]), "r"(b0), "r"(b1));
}
// per-lane ldmatrix.x4 address for a row-major 16x16 A tile (elements of 2 bytes)
template <typename T>
__device__ __forceinline__ uint32_t a_addr(const T* base, int LD, int rt16, int kcol, int lane) {
    int row = rt16 + (lane & 15);
    int col = kcol + ((lane >> 4) << 3);
    return smem_u32(base + row * LD + col);
}

__device__ __forceinline__ uint32_t pack_h2(float x, float y) {
    __half2 h = __floats2half2_rn(x, y); return *(uint32_t*)&h;
}
__device__ __forceinline__ uint32_t pack_b2(float x, float y) {
    __nv_bfloat162 h = __floats2bfloat162_rn(x, y); return *(uint32_t*)&h;
}
// pack one 16x16 B tile (W row-major [K][N]) into m16n8k16 col-major fragment regs
__device__ __forceinline__ uint4 pack_tile_h(const float* W, int N, int K0, int N0, int lane) {
    int g = lane >> 2, tig = lane & 3;
    int k0 = K0 + tig * 2;
    uint4 u;
    u.x = pack_h2(W[(size_t)k0 * N + N0 + g],       W[(size_t)(k0 + 1) * N + N0 + g]);
    u.y = pack_h2(W[(size_t)(k0 + 8) * N + N0 + g], W[(size_t)(k0 + 9) * N + N0 + g]);
    u.z = pack_h2(W[(size_t)k0 * N + N0 + 8 + g],       W[(size_t)(k0 + 1) * N + N0 + 8 + g]);
    u.w = pack_h2(W[(size_t)(k0 + 8) * N + N0 + 8 + g], W[(size_t)(k0 + 9) * N + N0 + 8 + g]);
    return u;
}
__device__ __forceinline__ uint4 pack_tile_b(const float* W, int N, int K0, int N0, int lane) {
    int g = lane >> 2, tig = lane & 3;
    int k0 = K0 + tig * 2;
    uint4 u;
    u.x = pack_b2(W[(size_t)k0 * N + N0 + g],       W[(size_t)(k0 + 1) * N + N0 + g]);
    u.y = pack_b2(W[(size_t)(k0 + 8) * N + N0 + g], W[(size_t)(k0 + 9) * N + N0 + g]);
    u.z = pack_b2(W[(size_t)k0 * N + N0 + 8 + g],       W[(size_t)(k0 + 1) * N + N0 + 8 + g]);
    u.w = pack_b2(W[(size_t)(k0 + 8) * N + N0 + 8 + g], W[(size_t)(k0 + 9) * N + N0 + 8 + g]);
    return u;
}

// ---------------- prelude: pack weights + bias table ----------------
#define N_BIAS 14406
#define PRE_TOT (N_QKVP + N_PROJP + N_FC1P + N_FC2P + N_BIAS)

__global__ void prelude(const float* __restrict__ qkvw, const float* __restrict__ projw,
                        const float* __restrict__ fc1w, const float* __restrict__ fc2w,
                        const float* __restrict__ rpb,  const int* __restrict__ relidx)
{
    int i = blockIdx.x * blockDim.x + threadIdx.x;
    if (i < N_QKVP) {
        int lane = i & 31, t = i >> 5, T = t / 12, K = t - T * 12;
        g_qkvp[i] = pack_tile_h(qkvw, 576, K * 16, T * 16, lane); return;
    }
    i -= N_QKVP;
    if (i < N_PROJP) {
        int lane = i & 31, t = i >> 5, T = t / 12, K = t - T * 12;
        g_projp[i] = pack_tile_h(projw, 192, K * 16, T * 16, lane); return;
    }
    i -= N_PROJP;
    if (i < N_FC1P) {
        int lane = i & 31, t = i >> 5, T = t / 12, K = t - T * 12;
        g_fc1p[i] = pack_tile_b(fc1w, 768, K * 16, T * 16, lane); return;
    }
    i -= N_FC1P;
    if (i < N_FC2P) {
        int lane = i & 31, t = i >> 5, T = t / 48, K = t - T * 48;
        g_fc2p[i] = pack_tile_b(fc2w, 192, K * 16, T * 16, lane); return;
    }
    i -= N_FC2P;
    if (i < N_BIAS) {
        int h = i / 2401, rj = i - h * 2401;
        g_bias[i] = rpb[relidx[rj] * 6 + h];
    }
}

// ============================================================================
// Kernel A: batched QKV GEMM, fp16 mma.sync (6272 CTAs, 256 thr, 2 CTAs/SM)
// smem: xnf f32[64][196]@0 (50176, st overlays); xh half[64][200]@50176. 75776
// ============================================================================
#define XN_LD 196
#define XH_LD 200
#define ST_LD 196
#define QKV_SMEM 75776

__global__ void __launch_bounds__(256, 2)
qkv_gemm(const float* __restrict__ x,
         const float* __restrict__ ln1w, const float* __restrict__ ln1b,
         const float* __restrict__ qkvb)
{
    extern __shared__ char smc[];
    float*  xnf = (float*)smc;
    float*  st  = (float*)smc;                 // overlay (used after LN1)
    __half* xh  = (__half*)(smc + 50176);

    const int tid  = threadIdx.x;
    const int wid  = tid >> 5;
    const int lane = tid & 31;
    const int t0   = blockIdx.x * 64;

    // gather x (fp32)
    {
        const int r = tid & 63;
        const int t = t0 + r;
        const int win = t / 49, pos = t - win * 49;
        const int b = win >> 10, wh = (win >> 5) & 31, ww = win & 31;
        const int pi = pos / 7;
        const float* src = x + (size_t)b * DIMC * HWSQ + (wh * 7 + pi) * HWI + (ww * 7 + pos - pi * 7);
        for (int c = tid >> 6; c < DIMC; c += 4)
            xnf[r * XN_LD + c] = src[(size_t)c * HWSQ];
    }
    __syncthreads();

    // LN1 (fp32 stats) -> fp16 A operand
    for (int r = wid; r < 64; r += 8) {
        float v[6]; float s = 0.f;
#pragma unroll
        for (int q = 0; q < 6; q++) { v[q] = xnf[r * XN_LD + lane + q * 32]; s += v[q]; }
#pragma unroll
        for (int o = 16; o; o >>= 1) s += __shfl_xor_sync(~0u, s, o);
        float mu = s * (1.f / 192.f);
        float vs = 0.f;
#pragma unroll
        for (int q = 0; q < 6; q++) { float d = v[q] - mu; vs += d * d; }
#pragma unroll
        for (int o = 16; o; o >>= 1) vs += __shfl_xor_sync(~0u, vs, o);
        float rs = rsqrtf(vs * (1.f / 192.f) + 1e-5f);
#pragma unroll
        for (int q = 0; q < 6; q++) {
            int c = lane + q * 32;
            xh[r * XH_LD + c] = __float2half_rn((v[q] - mu) * rs * ln1w[c] + ln1b[c]);
        }
    }
    __syncthreads();

    const int rtg = wid & 1;
    const int ctg = wid >> 1;
    const int gg = lane >> 2, tig = lane & 3;
    const float scale = 0.17677669529663687f;

    for (int chunk = 0; chunk < 3; chunk++) {
        float acc[2][3][2][4];
#pragma unroll
        for (int i = 0; i < 2; i++)
#pragma unroll
            for (int j = 0; j < 3; j++)
#pragma unroll
                for (int p = 0; p < 2; p++)
#pragma unroll
                    for (int q = 0; q < 4; q++) acc[i][j][p][q] = 0.f;

        uint4 wb[3];
#pragma unroll
        for (int j = 0; j < 3; j++)
            wb[j] = g_qkvp[((size_t)(chunk * 12 + ctg * 3 + j) * 12) * 32 + lane];

        for (int k = 0; k < 12; k++) {
            uint4 nb[3];
            if (k < 11) {
#pragma unroll
                for (int j = 0; j < 3; j++)
                    nb[j] = g_qkvp[((size_t)(chunk * 12 + ctg * 3 + j) * 12 + k + 1) * 32 + lane];
            }
            uint32_t RA[2][4];
#pragma unroll
            for (int i = 0; i < 2; i++)
                ldsm_x4(RA[i], a_addr(xh, XH_LD, rtg * 32 + i * 16, k * 16, lane));
#pragma unroll
            for (int j = 0; j < 3; j++)
#pragma unroll
                for (int i = 0; i < 2; i++) {
                    mma_h(acc[i][j][0], RA[i], wb[j].x, wb[j].y);
                    mma_h(acc[i][j][1], RA[i], wb[j].z, wb[j].w);
                }
            if (k < 11) { wb[0] = nb[0]; wb[1] = nb[1]; wb[2] = nb[2]; }
        }
        // store D -> st
#pragma unroll
        for (int i = 0; i < 2; i++)
#pragma unroll
            for (int j = 0; j < 3; j++)
#pragma unroll
                for (int p = 0; p < 2; p++) {
                    int col = (ctg * 3 + j) * 16 + p * 8 + tig * 2;
                    int row = rtg * 32 + i * 16 + gg;
                    *(float2*)(st + row * ST_LD + col)       = make_float2(acc[i][j][p][0], acc[i][j][p][1]);
                    *(float2*)(st + (row + 8) * ST_LD + col) = make_float2(acc[i][j][p][2], acc[i][j][p][3]);
                }
        __syncthreads();

        // epilogue (vectorized x4): bias, q-scale (chunk-uniform), fp16 round
        {
            const float sc = (chunk == 0) ? scale : 1.f;
            for (int idx = tid; idx < 64 * 48; idx += 256) {
                int r = idx / 48, c4 = (idx - r * 48) * 4;
                int gc = chunk * 192 + c4;
                float4 v  = *(const float4*)(st + r * ST_LD + c4);
                float4 bb = *(const float4*)(qkvb + gc);
                __half2 h0 = __floats2half2_rn((v.x + bb.x) * sc, (v.y + bb.y) * sc);
                __half2 h1 = __floats2half2_rn((v.z + bb.z) * sc, (v.w + bb.w) * sc);
                uint2 u; u.x = *(uint32_t*)&h0; u.y = *(uint32_t*)&h1;
                *(uint2*)(g_qkvh + (size_t)(t0 + r) * 576 + gc) = u;
            }
        }
        __syncthreads();
    }
}

// ============================================================================
// Kernel B: per window-head attention, fp16 (unchanged from round 14)
// ============================================================================
#define H_LDH 40
#define PB_LD 72
#define SC_LD 68
#define AH_SMEM 41984

__global__ void __launch_bounds__(128, 5)
attn_heads()
{
    extern __shared__ char smc[];
    __half* qs = (__half*)smc;
    __half* ks = (__half*)(smc + 5120);
    __half* vs = (__half*)(smc + 10240);
    __half* pb = (__half*)(smc + 15360);
    float*  sc = (float*)(smc + 24576);

    const int tid  = threadIdx.x;
    const int wid  = tid >> 5;
    const int lane = tid & 31;
    const int win  = blockIdx.x;
    const int h    = blockIdx.y;

    {
        const __half* base = g_qkvh + (size_t)win * 49 * 576 + h * 32;
        for (int idx = tid; idx < 3 * 49 * 4; idx += 128) {
            int m = idx / 196, rem = idx - m * 196;
            int r = rem >> 2, c8 = rem & 3;
            float4 v = *(const float4*)(base + (size_t)r * 576 + m * 192 + c8 * 8);
            __half* dst = (m == 0 ? qs : (m == 1 ? ks : vs));
            *(float4*)(dst + r * H_LDH + c8 * 8) = v;
        }
        float4 z = make_float4(0.f, 0.f, 0.f, 0.f);
        for (int idx = tid; idx < 3 * 15 * 4; idx += 128) {
            int m = idx / 60, rem = idx - m * 60;
            int r = 49 + (rem >> 2), c8 = rem & 3;
            __half* dst = (m == 0 ? qs : (m == 1 ? ks : vs));
            *(float4*)(dst + r * H_LDH + c8 * 8) = z;
        }
        for (int idx = tid; idx < 576; idx += 128)
            *(float4*)(pb + idx * 8) = z;
    }
    __syncthreads();

    {
        FragAh af[2];
#pragma unroll
        for (int k = 0; k < 2; k++)
            wmma::load_matrix_sync(af[k], qs + wid * 16 * H_LDH + k * 16, H_LDH);
#pragma unroll
        for (int ct = 0; ct < 4; ct++) {
            FragCf acc; wmma::fill_fragment(acc, 0.f);
#pragma unroll
            for (int k = 0; k < 2; k++) {
                FragBTh bf; wmma::load_matrix_sync(bf, ks + ct * 16 * H_LDH + k * 16, H_LDH);
                wmma::mma_sync(acc, af[k], bf, acc);
            }
            wmma::store_matrix_sync(sc + wid * 16 * SC_LD + ct * 16, acc, SC_LD, wmma::mem_row_major);
        }
    }
    __syncthreads();

    {
        const float* bh = g_bias + h * 2401;
        for (int r = wid; r < 49; r += 4) {
            float* srow = sc + r * SC_LD;
            int j0 = lane, j1 = lane + 32;
            float v0 = srow[j0] + bh[r * 49 + j0];
            float v1 = (j1 < 49) ? srow[j1] + bh[r * 49 + j1] : -1e30f;
            float m = fmaxf(v0, v1);
#pragma unroll
            for (int o = 16; o; o >>= 1) m = fmaxf(m, __shfl_xor_sync(~0u, m, o));
            float e0 = expf(v0 - m);
            float e1 = (j1 < 49) ? expf(v1 - m) : 0.f;
            float s = e0 + e1;
#pragma unroll
            for (int o = 16; o; o >>= 1) s += __shfl_xor_sync(~0u, s, o);
            float inv = 1.f / s;
            __half* prow = pb + r * PB_LD;
            prow[j0] = __float2half_rn(e0 * inv);
            if (j1 < 49) prow[j1] = __float2half_rn(e1 * inv);
        }
    }
    __syncthreads();

    {
        FragAh pf[4];
#pragma unroll
        for (int k = 0; k < 4; k++)
            wmma::load_matrix_sync(pf[k], pb + wid * 16 * PB_LD + k * 16, PB_LD);
#pragma unroll
        for (int ct = 0; ct < 2; ct++) {
            FragCf acc; wmma::fill_fragment(acc, 0.f);
#pragma unroll
            for (int k = 0; k < 4; k++) {
                FragBh bf; wmma::load_matrix_sync(bf, vs + k * 16 * H_LDH + ct * 16, H_LDH);
                wmma::mma_sync(acc, pf[k], bf, acc);
            }
            wmma::store_matrix_sync(sc + wid * 16 * SC_LD + ct * 16, acc, SC_LD, wmma::mem_row_major);
        }
    }
    __syncthreads();

    {
        __half* base = g_attnh + (size_t)win * 49 * DIMC + h * 32;
        for (int idx = tid; idx < 49 * 16; idx += 128) {
            int r = idx >> 4, c2 = idx & 15;
            __half2 h2 = __floats2half2_rn(sc[r * SC_LD + c2 * 2], sc[r * SC_LD + c2 * 2 + 1]);
            *(__half2*)(base + (size_t)r * DIMC + c2 * 2) = h2;
        }
    }
}

// ============================================================================
// Kernel C (FUSED): proj + residual + LN2 + MLP + out, mma.sync everywhere.
// smem layout (101376 B): xh@0 (25600) -> midb overlays; st@25600 (50176)
// -> mid overlays; as@75776 (25600).
// ============================================================================
#define PJ_LD 196
#define MD_LD 196
#define AS_LD 200
#define TAIL_SMEM 101376

__global__ void __launch_bounds__(256, 2)
tail_kernel(const float* __restrict__ x,
            const float* __restrict__ projb,
            const float* __restrict__ ln2w, const float* __restrict__ ln2b,
            const float* __restrict__ fc1b, const float* __restrict__ fc2b,
            float* __restrict__ out)
{
    extern __shared__ char smc[];
    __half* xh   = (__half*)smc;
    float*  st   = (float*)(smc + 25600);
    bf16*   as   = (bf16*)(smc + 75776);
    float*  mid  = (float*)(smc + 25600);   // overlays st (after LN2)
    bf16*   midb = (bf16*)smc;              // overlays xh (after proj GEMM)

    const int tid  = threadIdx.x;
    const int wid  = tid >> 5;
    const int lane = tid & 31;
    const int t0   = blockIdx.x * 64;
    const int rtg  = wid & 1;
    const int ctg  = wid >> 1;
    const int gg = lane >> 2, tig = lane & 3;

    // ---- load attn-out (fp16, coalesced) ----
    {
        const float4* src = (const float4*)(g_attnh + (size_t)t0 * DIMC);
        for (int idx = tid; idx < 64 * 24; idx += 256) {
            int r = idx / 24, c8 = idx - r * 24;
            *(float4*)(xh + r * XH_LD + c8 * 8) = src[idx];
        }
    }
    __syncthreads();

    // ---- proj GEMM fp16 mma.sync -> st ----
    {
        float acc[2][3][2][4];
#pragma unroll
        for (int i = 0; i < 2; i++)
#pragma unroll
            for (int j = 0; j < 3; j++)
#pragma unroll
                for (int p = 0; p < 2; p++)
#pragma unroll
                    for (int q = 0; q < 4; q++) acc[i][j][p][q] = 0.f;

        uint4 wb[3];
#pragma unroll
        for (int j = 0; j < 3; j++)
            wb[j] = g_projp[((size_t)(ctg * 3 + j) * 12) * 32 + lane];

        for (int k = 0; k < 12; k++) {
            uint4 nb[3];
            if (k < 11) {
#pragma unroll
                for (int j = 0; j < 3; j++)
                    nb[j] = g_projp[((size_t)(ctg * 3 + j) * 12 + k + 1) * 32 + lane];
            }
            uint32_t RA[2][4];
#pragma unroll
            for (int i = 0; i < 2; i++)
                ldsm_x4(RA[i], a_addr(xh, XH_LD, rtg * 32 + i * 16, k * 16, lane));
#pragma unroll
            for (int j = 0; j < 3; j++)
#pragma unroll
                for (int i = 0; i < 2; i++) {
                    mma_h(acc[i][j][0], RA[i], wb[j].x, wb[j].y);
                    mma_h(acc[i][j][1], RA[i], wb[j].z, wb[j].w);
                }
            if (k < 11) { wb[0] = nb[0]; wb[1] = nb[1]; wb[2] = nb[2]; }
        }
#pragma unroll
        for (int i = 0; i < 2; i++)
#pragma unroll
            for (int j = 0; j < 3; j++)
#pragma unroll
                for (int p = 0; p < 2; p++) {
                    int col = (ctg * 3 + j) * 16 + p * 8 + tig * 2;
                    int row = rtg * 32 + i * 16 + gg;
                    *(float2*)(st + row * PJ_LD + col)       = make_float2(acc[i][j][p][0], acc[i][j][p][1]);
                    *(float2*)(st + (row + 8) * PJ_LD + col) = make_float2(acc[i][j][p][2], acc[i][j][p][3]);
                }
    }
    __syncthreads();

    // ---- residual: st += x + projb ----
    {
        const int r = tid & 63;
        const int t = t0 + r;
        const int win = t / 49, pos = t - win * 49;
        const int b = win >> 10, wh = (win >> 5) & 31, ww = win & 31;
        const int pi = pos / 7;
        const float* src = x + (size_t)b * DIMC * HWSQ + (wh * 7 + pi) * HWI + (ww * 7 + pos - pi * 7);
        for (int c = tid >> 6; c < DIMC; c += 4)
            st[r * PJ_LD + c] += src[(size_t)c * HWSQ] + projb[c];
    }
    __syncthreads();

    // ---- LN2: h1 -> g_h1 (global), h1n -> as (smem bf16) ----
    for (int r = wid; r < 64; r += 8) {
        float v[6]; float s = 0.f;
#pragma unroll
        for (int q = 0; q < 6; q++) { v[q] = st[r * PJ_LD + lane + q * 32]; s += v[q]; }
#pragma unroll
        for (int o = 16; o; o >>= 1) s += __shfl_xor_sync(~0u, s, o);
        float mu = s * (1.f / 192.f);
        float vs = 0.f;
#pragma unroll
        for (int q = 0; q < 6; q++) { float d = v[q] - mu; vs += d * d; }
#pragma unroll
        for (int o = 16; o; o >>= 1) vs += __shfl_xor_sync(~0u, vs, o);
        float rs = rsqrtf(vs * (1.f / 192.f) + 1e-5f);
        size_t base = (size_t)(t0 + r) * DIMC;
#pragma unroll
        for (int q = 0; q < 6; q++) {
            int c = lane + q * 32;
            g_h1[base + c] = v[q];
            as[r * AS_LD + c] = __float2bfloat16((v[q] - mu) * rs * ln2w[c] + ln2b[c]);
        }
    }
    __syncthreads();   // st & xh now dead -> mid/midb overlays valid

    // ---- MLP: 4 K-chunks of 192, GEMM2 register-resident ----
    float acc2[2][3][2][4];
#pragma unroll
    for (int i = 0; i < 2; i++)
#pragma unroll
        for (int j = 0; j < 3; j++)
#pragma unroll
            for (int p = 0; p < 2; p++)
#pragma unroll
                for (int q = 0; q < 4; q++) acc2[i][j][p][q] = 0.f;

    for (int chunk = 0; chunk < 4; chunk++) {
        // GEMM1 bf16 mma.sync -> mid (no B double-buffer: register budget)
        {
            float acc[2][3][2][4];
#pragma unroll
            for (int i = 0; i < 2; i++)
#pragma unroll
                for (int j = 0; j < 3; j++)
#pragma unroll
                    for (int p = 0; p < 2; p++)
#pragma unroll
                        for (int q = 0; q < 4; q++) acc[i][j][p][q] = 0.f;

            for (int k = 0; k < 12; k++) {
                uint4 wb[3];
#pragma unroll
                for (int j = 0; j < 3; j++)
                    wb[j] = g_fc1p[((size_t)(chunk * 12 + ctg * 3 + j) * 12 + k) * 32 + lane];
                uint32_t RA[2][4];
#pragma unroll
                for (int i = 0; i < 2; i++)
                    ldsm_x4(RA[i], a_addr(as, AS_LD, rtg * 32 + i * 16, k * 16, lane));
#pragma unroll
                for (int j = 0; j < 3; j++)
#pragma unroll
                    for (int i = 0; i < 2; i++) {
                        mma_b(acc[i][j][0], RA[i], wb[j].x, wb[j].y);
                        mma_b(acc[i][j][1], RA[i], wb[j].z, wb[j].w);
                    }
            }
#pragma unroll
            for (int i = 0; i < 2; i++)
#pragma unroll
                for (int j = 0; j < 3; j++)
#pragma unroll
                    for (int p = 0; p < 2; p++) {
                        int col = (ctg * 3 + j) * 16 + p * 8 + tig * 2;
                        int row = rtg * 32 + i * 16 + gg;
                        *(float2*)(mid + row * MD_LD + col)       = make_float2(acc[i][j][p][0], acc[i][j][p][1]);
                        *(float2*)(mid + (row + 8) * MD_LD + col) = make_float2(acc[i][j][p][2], acc[i][j][p][3]);
                    }
        }
        __syncthreads();

        // bias + exact GELU -> midb bf16 (vectorized x4)
        for (int idx = tid; idx < 64 * 48; idx += 256) {
            int r = idx / 48, c4 = (idx - r * 48) * 4;
            float4 m  = *(const float4*)(mid + r * MD_LD + c4);
            float4 bb = *(const float4*)(fc1b + chunk * 192 + c4);
            float v0 = m.x + bb.x, v1 = m.y + bb.y, v2 = m.z + bb.z, v3 = m.w + bb.w;
            float g0 = 0.5f * v0 * (1.f + erff(v0 * 0.70710678118654752f));
            float g1 = 0.5f * v1 * (1.f + erff(v1 * 0.70710678118654752f));
            float g2 = 0.5f * v2 * (1.f + erff(v2 * 0.70710678118654752f));
            float g3 = 0.5f * v3 * (1.f + erff(v3 * 0.70710678118654752f));
            __nv_bfloat162 b0 = __floats2bfloat162_rn(g0, g1);
            __nv_bfloat162 b1 = __floats2bfloat162_rn(g2, g3);
            uint2 u; u.x = *(uint32_t*)&b0; u.y = *(uint32_t*)&b1;
            *(uint2*)(midb + r * AS_LD + c4) = u;
        }
        __syncthreads();

        // GEMM2 partial bf16 mma.sync (B double-buffered), acc2 persistent
        {
            uint4 wb[3];
#pragma unroll
            for (int j = 0; j < 3; j++)
                wb[j] = g_fc2p[((size_t)(ctg * 3 + j) * 48 + chunk * 12) * 32 + lane];
            for (int k = 0; k < 12; k++) {
                uint4 nb[3];
                if (k < 11) {
#pragma unroll
                    for (int j = 0; j < 3; j++)
                        nb[j] = g_fc2p[((size_t)(ctg * 3 + j) * 48 + chunk * 12 + k + 1) * 32 + lane];
                }
                uint32_t RA[2][4];
#pragma unroll
                for (int i = 0; i < 2; i++)
                    ldsm_x4(RA[i], a_addr(midb, AS_LD, rtg * 32 + i * 16, k * 16, lane));
#pragma unroll
                for (int j = 0; j < 3; j++)
#pragma unroll
                    for (int i = 0; i < 2; i++) {
                        mma_b(acc2[i][j][0], RA[i], wb[j].x, wb[j].y);
                        mma_b(acc2[i][j][1], RA[i], wb[j].z, wb[j].w);
                    }
                if (k < 11) { wb[0] = nb[0]; wb[1] = nb[1]; wb[2] = nb[2]; }
            }
        }
        __syncthreads();
    }

    // ---- store MLP output -> mid ----
#pragma unroll
    for (int i = 0; i < 2; i++)
#pragma unroll
        for (int j = 0; j < 3; j++)
#pragma unroll
            for (int p = 0; p < 2; p++) {
                int col = (ctg * 3 + j) * 16 + p * 8 + tig * 2;
                int row = rtg * 32 + i * 16 + gg;
                *(float2*)(mid + row * MD_LD + col)       = make_float2(acc2[i][j][p][0], acc2[i][j][p][1]);
                *(float2*)(mid + (row + 8) * MD_LD + col) = make_float2(acc2[i][j][p][2], acc2[i][j][p][3]);
            }
    __syncthreads();

    // ---- final pass 1 (c-fast, coalesced g_h1 reads): mid = (mid+h1)+fc2b ----
    for (int idx = tid; idx < 64 * 48; idx += 256) {
        int r = idx / 48, c4 = (idx - r * 48) * 4;
        float4 m  = *(const float4*)(mid + r * MD_LD + c4);
        float4 h  = *(const float4*)(g_h1 + (size_t)(t0 + r) * DIMC + c4);
        float4 bb = *(const float4*)(fc2b + c4);
        m.x = (m.x + h.x) + bb.x;
        m.y = (m.y + h.y) + bb.y;
        m.z = (m.z + h.z) + bb.z;
        m.w = (m.w + h.w) + bb.w;
        *(float4*)(mid + r * MD_LD + c4) = m;
    }
    __syncthreads();

    // ---- final pass 2 (r-fast): coalesced NCHW scatter ----
    for (int idx = tid; idx < 64 * 192; idx += 256) {
        int r = idx & 63;
        int c = idx >> 6;
        int t = t0 + r;
        int win = t / 49; int pos = t - win * 49;
        int b  = win >> 10;
        int wh = (win >> 5) & 31;
        int ww = win & 31;
        int pi = pos / 7;
        int hh = wh * 7 + pi;
        int wx = ww * 7 + (pos - pi * 7);
        out[((size_t)(b * DIMC + c)) * HWSQ + hh * HWI + wx] = mid[r * MD_LD + c];
    }
}

// ============================================================================
extern "C" void kernel_launch(void* const* d_in, const int* in_sizes, int n_in,
                              void* d_out, int out_size)
{
    (void)in_sizes; (void)n_in; (void)out_size;
    const float* x     = (const float*)d_in[0];
    const float* ln1w  = (const float*)d_in[1];
    const float* ln1b  = (const float*)d_in[2];
    const float* qkvw  = (const float*)d_in[3];
    const float* qkvb  = (const float*)d_in[4];
    const float* projw = (const float*)d_in[5];
    const float* projb = (const float*)d_in[6];
    const float* rpb   = (const float*)d_in[7];
    const float* ln2w  = (const float*)d_in[8];
    const float* ln2b  = (const float*)d_in[9];
    const float* fc1w  = (const float*)d_in[10];
    const float* fc1b  = (const float*)d_in[11];
    const float* fc2w  = (const float*)d_in[12];
    const float* fc2b  = (const float*)d_in[13];
    const int*   ridx  = (const int*)  d_in[14];
    float* out = (float*)d_out;

    cudaFuncSetAttribute(qkv_gemm,    cudaFuncAttributeMaxDynamicSharedMemorySize, QKV_SMEM);
    cudaFuncSetAttribute(attn_heads,  cudaFuncAttributeMaxDynamicSharedMemorySize, AH_SMEM);
    cudaFuncSetAttribute(tail_kernel, cudaFuncAttributeMaxDynamicSharedMemorySize, TAIL_SMEM);

    prelude<<<(PRE_TOT + 511) / 512, 512>>>(qkvw, projw, fc1w, fc2w, rpb, ridx);

    qkv_gemm<<<TTOK / 64, 256, QKV_SMEM>>>(x, ln1w, ln1b, qkvb);

    dim3 ag(NWIN, 6);
    attn_heads<<<ag, 128, AH_SMEM>>>();

    tail_kernel<<<TTOK / 64, 256, TAIL_SMEM>>>(x, projb, ln2w, ln2b, fc1b, fc2b, out);
}